// round 1
// baseline (speedup 1.0000x reference)
#include <cuda_runtime.h>

#define NEDGE 8192
#define DD    256
#define SPLITK 16

// Scratch (device globals; no allocation allowed)
__device__ float g_e[2][NEDGE][DD];            // e1, e2          (16 MB)
__device__ float g_Mpart[2][SPLITK][DD * DD];  // split-K partials (8 MB)
__device__ float g_M[2][DD * DD];              // M1, M2
__device__ float g_P[2][DD * DD];              // P1, P2

// ---------------------------------------------------------------------------
// Generic 128x128-tile fp32 GEMM block: C = act(A[M,K] @ B[K,N] + bias)
// 256 threads, 8x8 micro-tile per thread (2x2 quads of float4).
// ---------------------------------------------------------------------------
template <bool RELU>
__device__ __forceinline__ void gemm_tile_128(
    const float* __restrict__ A, int lda,
    const float* __restrict__ B, int ldb,
    const float* __restrict__ bias,
    float* __restrict__ C, int ldc,
    int K, int rowBase, int colBase)
{
    __shared__ float As[16][129];   // transposed A tile, padded (conflict-free scatter)
    __shared__ float Bs[16][132];   // row-major B tile, padded to keep 16B alignment

    const int tid = threadIdx.x;
    const int tx = tid & 15;
    const int ty = tid >> 4;

    float acc[8][8];
#pragma unroll
    for (int i = 0; i < 8; i++)
#pragma unroll
        for (int j = 0; j < 8; j++) acc[i][j] = 0.f;

    const int a_r = tid >> 2;        // 0..63
    const int a_c = (tid & 3) * 4;   // 0,4,8,12
    const int b_r = tid >> 5;        // 0..7
    const int b_c = (tid & 31) * 4;  // 0..124

    for (int kt = 0; kt < K; kt += 16) {
#pragma unroll
        for (int rr = 0; rr < 128; rr += 64) {
            const float4 v = *(const float4*)&A[(size_t)(rowBase + a_r + rr) * lda + kt + a_c];
            As[a_c + 0][a_r + rr] = v.x;
            As[a_c + 1][a_r + rr] = v.y;
            As[a_c + 2][a_r + rr] = v.z;
            As[a_c + 3][a_r + rr] = v.w;
        }
#pragma unroll
        for (int rr = 0; rr < 16; rr += 8) {
            const float4 v = *(const float4*)&B[(size_t)(kt + b_r + rr) * ldb + colBase + b_c];
            *(float4*)&Bs[b_r + rr][b_c] = v;
        }
        __syncthreads();
#pragma unroll
        for (int kk = 0; kk < 16; kk++) {
            float ra[8], rb[8];
#pragma unroll
            for (int i = 0; i < 4; i++) {
                ra[i]     = As[kk][ty * 4 + i];
                ra[4 + i] = As[kk][64 + ty * 4 + i];
            }
            const float4 b0 = *(const float4*)&Bs[kk][tx * 4];
            const float4 b1 = *(const float4*)&Bs[kk][64 + tx * 4];
            rb[0] = b0.x; rb[1] = b0.y; rb[2] = b0.z; rb[3] = b0.w;
            rb[4] = b1.x; rb[5] = b1.y; rb[6] = b1.z; rb[7] = b1.w;
#pragma unroll
            for (int i = 0; i < 8; i++)
#pragma unroll
                for (int j = 0; j < 8; j++)
                    acc[i][j] = fmaf(ra[i], rb[j], acc[i][j]);
        }
        __syncthreads();
    }

#pragma unroll
    for (int ih = 0; ih < 2; ih++) {
#pragma unroll
        for (int i = 0; i < 4; i++) {
            const int r = rowBase + ih * 64 + ty * 4 + i;
#pragma unroll
            for (int jh = 0; jh < 2; jh++) {
                const int c = colBase + jh * 64 + tx * 4;
                float4 v;
                v.x = acc[ih * 4 + i][jh * 4 + 0];
                v.y = acc[ih * 4 + i][jh * 4 + 1];
                v.z = acc[ih * 4 + i][jh * 4 + 2];
                v.w = acc[ih * 4 + i][jh * 4 + 3];
                if (bias) {
                    const float4 bb = *(const float4*)&bias[c];
                    v.x += bb.x; v.y += bb.y; v.z += bb.z; v.w += bb.w;
                }
                if (RELU) {
                    v.x = fmaxf(v.x, 0.f); v.y = fmaxf(v.y, 0.f);
                    v.z = fmaxf(v.z, 0.f); v.w = fmaxf(v.w, 0.f);
                }
                *(float4*)&C[(size_t)r * ldc + c] = v;
            }
        }
    }
}

// ---------------------------------------------------------------------------
// Kernel 1: e_z = relu(X @ W_z + b_z),  z in {0,1}. grid (2, 64, 2)
// ---------------------------------------------------------------------------
__global__ void k_e(const float* __restrict__ X,
                    const float* __restrict__ W1, const float* __restrict__ b1,
                    const float* __restrict__ W2, const float* __restrict__ b2)
{
    const int z = blockIdx.z;
    gemm_tile_128<true>(X, DD,
                        z ? W2 : W1, DD,
                        z ? b2 : b1,
                        &g_e[z][0][0], DD,
                        DD, blockIdx.y * 128, blockIdx.x * 128);
}

// ---------------------------------------------------------------------------
// Kernel 2: split-K partials of M_z = e_zᵀ @ X   (output 256x256, K=8192)
// grid (4, 4, 2*SPLITK), 256 threads, 64x64 out tile, 4x4 micro.
// ---------------------------------------------------------------------------
__global__ void k_mpart(const float* __restrict__ X)
{
    const int z = blockIdx.z;
    const int mat = z >> 4;
    const int split = z & (SPLITK - 1);
    const float* __restrict__ E = &g_e[mat][0][0];
    float* __restrict__ Cp = &g_Mpart[mat][split][0];

    __shared__ float Es[16][68];
    __shared__ float Xs[16][68];

    const int tid = threadIdx.x;
    const int tx = tid & 15;
    const int ty = tid >> 4;
    const int kBase = blockIdx.y * 64;   // output row (k-dim of E)
    const int jBase = blockIdx.x * 64;   // output col (feature of X)
    const int lr = tid >> 4;             // 0..15
    const int lc = (tid & 15) * 4;       // 0..60

    float acc[4][4] = {};

    const int CHUNK = NEDGE / SPLITK;    // 512
    const int i0 = split * CHUNK;
    for (int it = i0; it < i0 + CHUNK; it += 16) {
        *(float4*)&Es[lr][lc] = *(const float4*)&E[(size_t)(it + lr) * DD + kBase + lc];
        *(float4*)&Xs[lr][lc] = *(const float4*)&X[(size_t)(it + lr) * DD + jBase + lc];
        __syncthreads();
#pragma unroll
        for (int ii = 0; ii < 16; ii++) {
            const float4 ra = *(const float4*)&Es[ii][ty * 4];
            const float4 rb = *(const float4*)&Xs[ii][tx * 4];
            const float a[4] = {ra.x, ra.y, ra.z, ra.w};
            const float b[4] = {rb.x, rb.y, rb.z, rb.w};
#pragma unroll
            for (int i = 0; i < 4; i++)
#pragma unroll
                for (int j = 0; j < 4; j++)
                    acc[i][j] = fmaf(a[i], b[j], acc[i][j]);
        }
        __syncthreads();
    }
#pragma unroll
    for (int i = 0; i < 4; i++) {
        float4 v = make_float4(acc[i][0], acc[i][1], acc[i][2], acc[i][3]);
        *(float4*)&Cp[(size_t)(kBase + ty * 4 + i) * DD + jBase + tx * 4] = v;
    }
}

// ---------------------------------------------------------------------------
// Kernel 3: deterministic reduce of split-K partials, scale by 1/D.
// ---------------------------------------------------------------------------
__global__ void k_mreduce()
{
    const int idx = blockIdx.x * 256 + threadIdx.x;  // 0 .. 2*65536-1
    const int mat = idx >> 16;
    const int o = idx & 0xFFFF;
    float s = 0.f;
#pragma unroll
    for (int p = 0; p < SPLITK; p++) s += g_Mpart[mat][p][o];
    g_M[mat][o] = s * (1.0f / DD);
}

// ---------------------------------------------------------------------------
// Kernel 4: P_z = M_z @ W3[(1+z)*256 : (2+z)*256].  grid (2, 2, 2)
// ---------------------------------------------------------------------------
__global__ void k_p(const float* __restrict__ W3)
{
    const int z = blockIdx.z;
    gemm_tile_128<false>(g_M[z], DD,
                         W3 + (size_t)(DD + z * DD) * DD, DD,
                         nullptr,
                         g_P[z], DD,
                         DD, blockIdx.y * 128, blockIdx.x * 128);
}

// ---------------------------------------------------------------------------
// Kernel 5: out = relu(X@W3a + e1@P1 + e2@P2 + b3) as K=768 GEMM with
// per-256-chunk source selection. grid (2, 64)
// ---------------------------------------------------------------------------
__global__ void k_final(const float* __restrict__ X,
                        const float* __restrict__ W3, const float* __restrict__ b3,
                        float* __restrict__ out)
{
    __shared__ float As[16][129];
    __shared__ float Bs[16][132];

    const float* __restrict__ Asrc[3] = {X, &g_e[0][0][0], &g_e[1][0][0]};
    const float* __restrict__ Bsrc[3] = {W3, g_P[0], g_P[1]};

    const int tid = threadIdx.x;
    const int tx = tid & 15;
    const int ty = tid >> 4;
    const int rowBase = blockIdx.y * 128;
    const int colBase = blockIdx.x * 128;

    float acc[8][8];
#pragma unroll
    for (int i = 0; i < 8; i++)
#pragma unroll
        for (int j = 0; j < 8; j++) acc[i][j] = 0.f;

    const int a_r = tid >> 2;
    const int a_c = (tid & 3) * 4;
    const int b_r = tid >> 5;
    const int b_c = (tid & 31) * 4;

    for (int kt = 0; kt < 768; kt += 16) {
        const int src = kt >> 8;
        const int kc = kt & 255;
        const float* __restrict__ A = Asrc[src];
        const float* __restrict__ B = Bsrc[src];
#pragma unroll
        for (int rr = 0; rr < 128; rr += 64) {
            const float4 v = *(const float4*)&A[(size_t)(rowBase + a_r + rr) * DD + kc + a_c];
            As[a_c + 0][a_r + rr] = v.x;
            As[a_c + 1][a_r + rr] = v.y;
            As[a_c + 2][a_r + rr] = v.z;
            As[a_c + 3][a_r + rr] = v.w;
        }
#pragma unroll
        for (int rr = 0; rr < 16; rr += 8) {
            const float4 v = *(const float4*)&B[(size_t)(kc + b_r + rr) * DD + colBase + b_c];
            *(float4*)&Bs[b_r + rr][b_c] = v;
        }
        __syncthreads();
#pragma unroll
        for (int kk = 0; kk < 16; kk++) {
            float ra[8], rb[8];
#pragma unroll
            for (int i = 0; i < 4; i++) {
                ra[i]     = As[kk][ty * 4 + i];
                ra[4 + i] = As[kk][64 + ty * 4 + i];
            }
            const float4 bq0 = *(const float4*)&Bs[kk][tx * 4];
            const float4 bq1 = *(const float4*)&Bs[kk][64 + tx * 4];
            rb[0] = bq0.x; rb[1] = bq0.y; rb[2] = bq0.z; rb[3] = bq0.w;
            rb[4] = bq1.x; rb[5] = bq1.y; rb[6] = bq1.z; rb[7] = bq1.w;
#pragma unroll
            for (int i = 0; i < 8; i++)
#pragma unroll
                for (int j = 0; j < 8; j++)
                    acc[i][j] = fmaf(ra[i], rb[j], acc[i][j]);
        }
        __syncthreads();
    }

#pragma unroll
    for (int ih = 0; ih < 2; ih++) {
#pragma unroll
        for (int i = 0; i < 4; i++) {
            const int r = rowBase + ih * 64 + ty * 4 + i;
#pragma unroll
            for (int jh = 0; jh < 2; jh++) {
                const int c = colBase + jh * 64 + tx * 4;
                const float4 bb = *(const float4*)&b3[c];
                float4 v;
                v.x = fmaxf(acc[ih * 4 + i][jh * 4 + 0] + bb.x, 0.f);
                v.y = fmaxf(acc[ih * 4 + i][jh * 4 + 1] + bb.y, 0.f);
                v.z = fmaxf(acc[ih * 4 + i][jh * 4 + 2] + bb.z, 0.f);
                v.w = fmaxf(acc[ih * 4 + i][jh * 4 + 3] + bb.w, 0.f);
                *(float4*)&out[(size_t)r * DD + c] = v;
            }
        }
    }
}

// ---------------------------------------------------------------------------
// Inputs (metadata order):
// 0 edge_pred[8192] f32 | 1 edge_corner[8192,2] i64 | 2 all_corners[4096,2] f32
// 3 edge_x[8192,256] f32 | 4 image_x[1024] f32 | 5 W1[256,256] | 6 b1[256]
// 7 W2[256,256] | 8 b2[256] | 9 W3[768,256] | 10 b3[256]
// Output: [8192, 256] f32
// ---------------------------------------------------------------------------
extern "C" void kernel_launch(void* const* d_in, const int* in_sizes, int n_in,
                              void* d_out, int out_size)
{
    (void)in_sizes; (void)n_in; (void)out_size;
    const float* X  = (const float*)d_in[3];
    const float* W1 = (const float*)d_in[5];
    const float* b1 = (const float*)d_in[6];
    const float* W2 = (const float*)d_in[7];
    const float* b2 = (const float*)d_in[8];
    const float* W3 = (const float*)d_in[9];
    const float* b3 = (const float*)d_in[10];
    float* out = (float*)d_out;

    k_e<<<dim3(2, 64, 2), 256>>>(X, W1, b1, W2, b2);
    k_mpart<<<dim3(4, 4, 2 * SPLITK), 256>>>(X);
    k_mreduce<<<512, 256>>>();
    k_p<<<dim3(2, 2, 2), 256>>>(W3);
    k_final<<<dim3(2, 64), 256>>>(X, W3, b3, out);
}

// round 2
// speedup vs baseline: 1.3749x; 1.3749x over previous
#include <cuda_runtime.h>

#define NEDGE 8192
#define DD    256
#define SPLITK 16

// Scratch (device globals; no allocation allowed)
__device__ float g_e[2][NEDGE][DD];            // e1, e2          (16 MB)
__device__ float g_Mpart[2][SPLITK][DD * DD];  // split-K partials (8 MB)
__device__ float g_M[2][DD * DD];              // M1, M2
__device__ float g_P[2][DD * DD];              // P1, P2

// ---------------------------------------------------------------------------
// Double-buffered 128x128-tile fp32 GEMM: C = act(A[M,K] @ B[K,N] + bias)
// 256 threads, 8x8 micro-tile per thread.
// ---------------------------------------------------------------------------
template <bool RELU>
__device__ __forceinline__ void gemm_tile_128(
    const float* __restrict__ A, int lda,
    const float* __restrict__ B, int ldb,
    const float* __restrict__ bias,
    float* __restrict__ C, int ldc,
    int K, int rowBase, int colBase)
{
    __shared__ __align__(16) float As[2][16][129];   // transposed A tile
    __shared__ __align__(16) float Bs[2][16][132];   // row-major B tile

    const int tid = threadIdx.x;
    const int tx = tid & 15;
    const int ty = tid >> 4;

    float acc[8][8];
#pragma unroll
    for (int i = 0; i < 8; i++)
#pragma unroll
        for (int j = 0; j < 8; j++) acc[i][j] = 0.f;

    const int a_r = tid >> 2;        // 0..63
    const int a_c = (tid & 3) * 4;   // 0,4,8,12
    const int b_r = tid >> 5;        // 0..7
    const int b_c = (tid & 31) * 4;  // 0..124

    // Preload k-tile 0 into buffer 0
    float4 av0 = *(const float4*)&A[(size_t)(rowBase + a_r) * lda + a_c];
    float4 av1 = *(const float4*)&A[(size_t)(rowBase + a_r + 64) * lda + a_c];
    float4 bv0 = *(const float4*)&B[(size_t)(b_r) * ldb + colBase + b_c];
    float4 bv1 = *(const float4*)&B[(size_t)(b_r + 8) * ldb + colBase + b_c];
    As[0][a_c + 0][a_r] = av0.x; As[0][a_c + 1][a_r] = av0.y;
    As[0][a_c + 2][a_r] = av0.z; As[0][a_c + 3][a_r] = av0.w;
    As[0][a_c + 0][a_r + 64] = av1.x; As[0][a_c + 1][a_r + 64] = av1.y;
    As[0][a_c + 2][a_r + 64] = av1.z; As[0][a_c + 3][a_r + 64] = av1.w;
    *(float4*)&Bs[0][b_r][b_c] = bv0;
    *(float4*)&Bs[0][b_r + 8][b_c] = bv1;
    __syncthreads();

    int buf = 0;
    for (int kt = 16; kt <= K; kt += 16) {
        const bool more = (kt < K);
        if (more) {
            av0 = *(const float4*)&A[(size_t)(rowBase + a_r) * lda + kt + a_c];
            av1 = *(const float4*)&A[(size_t)(rowBase + a_r + 64) * lda + kt + a_c];
            bv0 = *(const float4*)&B[(size_t)(kt + b_r) * ldb + colBase + b_c];
            bv1 = *(const float4*)&B[(size_t)(kt + b_r + 8) * ldb + colBase + b_c];
        }
#pragma unroll
        for (int kk = 0; kk < 16; kk++) {
            float ra[8], rb[8];
#pragma unroll
            for (int i = 0; i < 4; i++) {
                ra[i]     = As[buf][kk][ty * 4 + i];
                ra[4 + i] = As[buf][kk][64 + ty * 4 + i];
            }
            const float4 q0 = *(const float4*)&Bs[buf][kk][tx * 4];
            const float4 q1 = *(const float4*)&Bs[buf][kk][64 + tx * 4];
            rb[0] = q0.x; rb[1] = q0.y; rb[2] = q0.z; rb[3] = q0.w;
            rb[4] = q1.x; rb[5] = q1.y; rb[6] = q1.z; rb[7] = q1.w;
#pragma unroll
            for (int i = 0; i < 8; i++)
#pragma unroll
                for (int j = 0; j < 8; j++)
                    acc[i][j] = fmaf(ra[i], rb[j], acc[i][j]);
        }
        if (more) {
            const int nb = buf ^ 1;
            As[nb][a_c + 0][a_r] = av0.x; As[nb][a_c + 1][a_r] = av0.y;
            As[nb][a_c + 2][a_r] = av0.z; As[nb][a_c + 3][a_r] = av0.w;
            As[nb][a_c + 0][a_r + 64] = av1.x; As[nb][a_c + 1][a_r + 64] = av1.y;
            As[nb][a_c + 2][a_r + 64] = av1.z; As[nb][a_c + 3][a_r + 64] = av1.w;
            *(float4*)&Bs[nb][b_r][b_c] = bv0;
            *(float4*)&Bs[nb][b_r + 8][b_c] = bv1;
            __syncthreads();
            buf = nb;
        }
    }

#pragma unroll
    for (int ih = 0; ih < 2; ih++) {
#pragma unroll
        for (int i = 0; i < 4; i++) {
            const int r = rowBase + ih * 64 + ty * 4 + i;
#pragma unroll
            for (int jh = 0; jh < 2; jh++) {
                const int c = colBase + jh * 64 + tx * 4;
                float4 v;
                v.x = acc[ih * 4 + i][jh * 4 + 0];
                v.y = acc[ih * 4 + i][jh * 4 + 1];
                v.z = acc[ih * 4 + i][jh * 4 + 2];
                v.w = acc[ih * 4 + i][jh * 4 + 3];
                if (bias) {
                    const float4 bb = *(const float4*)&bias[c];
                    v.x += bb.x; v.y += bb.y; v.z += bb.z; v.w += bb.w;
                }
                if (RELU) {
                    v.x = fmaxf(v.x, 0.f); v.y = fmaxf(v.y, 0.f);
                    v.z = fmaxf(v.z, 0.f); v.w = fmaxf(v.w, 0.f);
                }
                *(float4*)&C[(size_t)r * ldc + c] = v;
            }
        }
    }
}

// ---------------------------------------------------------------------------
// Kernel 1: e_z = relu(X @ W_z + b_z). grid (2, 64, 2)
// ---------------------------------------------------------------------------
__global__ void __launch_bounds__(256, 2)
k_e(const float* __restrict__ X,
    const float* __restrict__ W1, const float* __restrict__ b1,
    const float* __restrict__ W2, const float* __restrict__ b2)
{
    const int z = blockIdx.z;
    gemm_tile_128<true>(X, DD,
                        z ? W2 : W1, DD,
                        z ? b2 : b1,
                        &g_e[z][0][0], DD,
                        DD, blockIdx.y * 128, blockIdx.x * 128);
}

// ---------------------------------------------------------------------------
// Kernel 2: split-K partials of M_z = e_zᵀ @ X.  Both operands contiguous
// (k = edge index is the slow dim of both E and X). 128x128 out tile,
// 8x8 micro, double-buffered. grid (2, 2, 2*SPLITK)
// ---------------------------------------------------------------------------
__global__ void __launch_bounds__(256, 2)
k_mpart(const float* __restrict__ X)
{
    const int mat = blockIdx.z >> 4;
    const int split = blockIdx.z & (SPLITK - 1);
    const float* __restrict__ E = &g_e[mat][0][0];
    float* __restrict__ Cp = &g_Mpart[mat][split][0];

    __shared__ __align__(16) float Es[2][16][132];
    __shared__ __align__(16) float Xs[2][16][132];

    const int tid = threadIdx.x;
    const int tx = tid & 15;
    const int ty = tid >> 4;
    const int kBase = blockIdx.y * 128;  // output row (col of E)
    const int jBase = blockIdx.x * 128;  // output col (col of X)
    const int lr = tid >> 5;             // 0..7
    const int lc = (tid & 31) * 4;       // 0..124

    float acc[8][8];
#pragma unroll
    for (int i = 0; i < 8; i++)
#pragma unroll
        for (int j = 0; j < 8; j++) acc[i][j] = 0.f;

    const int CHUNK = NEDGE / SPLITK;    // 512
    const int i0 = split * CHUNK;

    float4 ev0 = *(const float4*)&E[(size_t)(i0 + lr) * DD + kBase + lc];
    float4 ev1 = *(const float4*)&E[(size_t)(i0 + lr + 8) * DD + kBase + lc];
    float4 xv0 = *(const float4*)&X[(size_t)(i0 + lr) * DD + jBase + lc];
    float4 xv1 = *(const float4*)&X[(size_t)(i0 + lr + 8) * DD + jBase + lc];
    *(float4*)&Es[0][lr][lc] = ev0;  *(float4*)&Es[0][lr + 8][lc] = ev1;
    *(float4*)&Xs[0][lr][lc] = xv0;  *(float4*)&Xs[0][lr + 8][lc] = xv1;
    __syncthreads();

    int buf = 0;
    for (int it = 16; it <= CHUNK; it += 16) {
        const bool more = (it < CHUNK);
        if (more) {
            ev0 = *(const float4*)&E[(size_t)(i0 + it + lr) * DD + kBase + lc];
            ev1 = *(const float4*)&E[(size_t)(i0 + it + lr + 8) * DD + kBase + lc];
            xv0 = *(const float4*)&X[(size_t)(i0 + it + lr) * DD + jBase + lc];
            xv1 = *(const float4*)&X[(size_t)(i0 + it + lr + 8) * DD + jBase + lc];
        }
#pragma unroll
        for (int kk = 0; kk < 16; kk++) {
            float ra[8], rb[8];
            const float4 a0 = *(const float4*)&Es[buf][kk][ty * 4];
            const float4 a1 = *(const float4*)&Es[buf][kk][64 + ty * 4];
            const float4 b0 = *(const float4*)&Xs[buf][kk][tx * 4];
            const float4 b1 = *(const float4*)&Xs[buf][kk][64 + tx * 4];
            ra[0] = a0.x; ra[1] = a0.y; ra[2] = a0.z; ra[3] = a0.w;
            ra[4] = a1.x; ra[5] = a1.y; ra[6] = a1.z; ra[7] = a1.w;
            rb[0] = b0.x; rb[1] = b0.y; rb[2] = b0.z; rb[3] = b0.w;
            rb[4] = b1.x; rb[5] = b1.y; rb[6] = b1.z; rb[7] = b1.w;
#pragma unroll
            for (int i = 0; i < 8; i++)
#pragma unroll
                for (int j = 0; j < 8; j++)
                    acc[i][j] = fmaf(ra[i], rb[j], acc[i][j]);
        }
        if (more) {
            const int nb = buf ^ 1;
            *(float4*)&Es[nb][lr][lc] = ev0;  *(float4*)&Es[nb][lr + 8][lc] = ev1;
            *(float4*)&Xs[nb][lr][lc] = xv0;  *(float4*)&Xs[nb][lr + 8][lc] = xv1;
            __syncthreads();
            buf = nb;
        }
    }

#pragma unroll
    for (int ih = 0; ih < 2; ih++) {
#pragma unroll
        for (int i = 0; i < 4; i++) {
            const int r = kBase + ih * 64 + ty * 4 + i;
#pragma unroll
            for (int jh = 0; jh < 2; jh++) {
                const int c = jBase + jh * 64 + tx * 4;
                float4 v;
                v.x = acc[ih * 4 + i][jh * 4 + 0];
                v.y = acc[ih * 4 + i][jh * 4 + 1];
                v.z = acc[ih * 4 + i][jh * 4 + 2];
                v.w = acc[ih * 4 + i][jh * 4 + 3];
                *(float4*)&Cp[(size_t)r * DD + c] = v;
            }
        }
    }
}

// ---------------------------------------------------------------------------
// Kernel 3: deterministic reduce of split-K partials, scale by 1/D.
// ---------------------------------------------------------------------------
__global__ void k_mreduce()
{
    const int idx = blockIdx.x * 256 + threadIdx.x;
    const int mat = idx >> 16;
    const int o = idx & 0xFFFF;
    float s = 0.f;
#pragma unroll
    for (int p = 0; p < SPLITK; p++) s += g_Mpart[mat][p][o];
    g_M[mat][o] = s * (1.0f / DD);
}

// ---------------------------------------------------------------------------
// Kernel 4: P_z = M_z @ W3[(1+z)*256 : (2+z)*256].
// 64x64 tiles, 4x4 micro -> grid (4, 4, 2) = 32 blocks (was 8: latency-bound).
// ---------------------------------------------------------------------------
__global__ void k_p(const float* __restrict__ W3)
{
    const int z = blockIdx.z;
    const float* __restrict__ A = g_M[z];
    const float* __restrict__ B = W3 + (size_t)(DD + z * DD) * DD;
    float* __restrict__ C = g_P[z];

    __shared__ __align__(16) float As[16][65];
    __shared__ __align__(16) float Bs[16][68];

    const int tid = threadIdx.x;
    const int tx = tid & 15;
    const int ty = tid >> 4;
    const int rowBase = blockIdx.y * 64;
    const int colBase = blockIdx.x * 64;

    const int a_r = tid >> 2;        // 0..63
    const int a_c = (tid & 3) * 4;   // 0..12
    const int b_r = tid >> 4;        // 0..15
    const int b_c = (tid & 15) * 4;  // 0..60

    float acc[4][4] = {};

    for (int kt = 0; kt < DD; kt += 16) {
        const float4 av = *(const float4*)&A[(size_t)(rowBase + a_r) * DD + kt + a_c];
        As[a_c + 0][a_r] = av.x; As[a_c + 1][a_r] = av.y;
        As[a_c + 2][a_r] = av.z; As[a_c + 3][a_r] = av.w;
        *(float4*)&Bs[b_r][b_c] = *(const float4*)&B[(size_t)(kt + b_r) * DD + colBase + b_c];
        __syncthreads();
#pragma unroll
        for (int kk = 0; kk < 16; kk++) {
            float a[4], b[4];
#pragma unroll
            for (int i = 0; i < 4; i++) a[i] = As[kk][ty * 4 + i];
            const float4 bq = *(const float4*)&Bs[kk][tx * 4];
            b[0] = bq.x; b[1] = bq.y; b[2] = bq.z; b[3] = bq.w;
#pragma unroll
            for (int i = 0; i < 4; i++)
#pragma unroll
                for (int j = 0; j < 4; j++)
                    acc[i][j] = fmaf(a[i], b[j], acc[i][j]);
        }
        __syncthreads();
    }
#pragma unroll
    for (int i = 0; i < 4; i++) {
        float4 v = make_float4(acc[i][0], acc[i][1], acc[i][2], acc[i][3]);
        *(float4*)&C[(size_t)(rowBase + ty * 4 + i) * DD + colBase + tx * 4] = v;
    }
}

// ---------------------------------------------------------------------------
// Kernel 5: out = relu(X@W3a + e1@P1 + e2@P2 + b3) as K=768 GEMM with
// per-256-chunk source selection, double-buffered. grid (2, 64)
// ---------------------------------------------------------------------------
__global__ void __launch_bounds__(256, 2)
k_final(const float* __restrict__ X,
        const float* __restrict__ W3, const float* __restrict__ b3,
        float* __restrict__ out)
{
    __shared__ __align__(16) float As[2][16][129];
    __shared__ __align__(16) float Bs[2][16][132];

    const float* __restrict__ Asrc[3] = {X, &g_e[0][0][0], &g_e[1][0][0]};
    const float* __restrict__ Bsrc[3] = {W3, g_P[0], g_P[1]};

    const int tid = threadIdx.x;
    const int tx = tid & 15;
    const int ty = tid >> 4;
    const int rowBase = blockIdx.y * 128;
    const int colBase = blockIdx.x * 128;

    float acc[8][8];
#pragma unroll
    for (int i = 0; i < 8; i++)
#pragma unroll
        for (int j = 0; j < 8; j++) acc[i][j] = 0.f;

    const int a_r = tid >> 2;
    const int a_c = (tid & 3) * 4;
    const int b_r = tid >> 5;
    const int b_c = (tid & 31) * 4;

    // Preload chunk 0 (src 0)
    float4 av0 = *(const float4*)&Asrc[0][(size_t)(rowBase + a_r) * DD + a_c];
    float4 av1 = *(const float4*)&Asrc[0][(size_t)(rowBase + a_r + 64) * DD + a_c];
    float4 bv0 = *(const float4*)&Bsrc[0][(size_t)(b_r) * DD + colBase + b_c];
    float4 bv1 = *(const float4*)&Bsrc[0][(size_t)(b_r + 8) * DD + colBase + b_c];
    As[0][a_c + 0][a_r] = av0.x; As[0][a_c + 1][a_r] = av0.y;
    As[0][a_c + 2][a_r] = av0.z; As[0][a_c + 3][a_r] = av0.w;
    As[0][a_c + 0][a_r + 64] = av1.x; As[0][a_c + 1][a_r + 64] = av1.y;
    As[0][a_c + 2][a_r + 64] = av1.z; As[0][a_c + 3][a_r + 64] = av1.w;
    *(float4*)&Bs[0][b_r][b_c] = bv0;
    *(float4*)&Bs[0][b_r + 8][b_c] = bv1;
    __syncthreads();

    int buf = 0;
    for (int kt = 16; kt <= 768; kt += 16) {
        const bool more = (kt < 768);
        if (more) {
            const int src = kt >> 8;
            const int kc = kt & 255;
            const float* __restrict__ A = Asrc[src];
            const float* __restrict__ B = Bsrc[src];
            av0 = *(const float4*)&A[(size_t)(rowBase + a_r) * DD + kc + a_c];
            av1 = *(const float4*)&A[(size_t)(rowBase + a_r + 64) * DD + kc + a_c];
            bv0 = *(const float4*)&B[(size_t)(kc + b_r) * DD + colBase + b_c];
            bv1 = *(const float4*)&B[(size_t)(kc + b_r + 8) * DD + colBase + b_c];
        }
#pragma unroll
        for (int kk = 0; kk < 16; kk++) {
            float ra[8], rb[8];
#pragma unroll
            for (int i = 0; i < 4; i++) {
                ra[i]     = As[buf][kk][ty * 4 + i];
                ra[4 + i] = As[buf][kk][64 + ty * 4 + i];
            }
            const float4 q0 = *(const float4*)&Bs[buf][kk][tx * 4];
            const float4 q1 = *(const float4*)&Bs[buf][kk][64 + tx * 4];
            rb[0] = q0.x; rb[1] = q0.y; rb[2] = q0.z; rb[3] = q0.w;
            rb[4] = q1.x; rb[5] = q1.y; rb[6] = q1.z; rb[7] = q1.w;
#pragma unroll
            for (int i = 0; i < 8; i++)
#pragma unroll
                for (int j = 0; j < 8; j++)
                    acc[i][j] = fmaf(ra[i], rb[j], acc[i][j]);
        }
        if (more) {
            const int nb = buf ^ 1;
            As[nb][a_c + 0][a_r] = av0.x; As[nb][a_c + 1][a_r] = av0.y;
            As[nb][a_c + 2][a_r] = av0.z; As[nb][a_c + 3][a_r] = av0.w;
            As[nb][a_c + 0][a_r + 64] = av1.x; As[nb][a_c + 1][a_r + 64] = av1.y;
            As[nb][a_c + 2][a_r + 64] = av1.z; As[nb][a_c + 3][a_r + 64] = av1.w;
            *(float4*)&Bs[nb][b_r][b_c] = bv0;
            *(float4*)&Bs[nb][b_r + 8][b_c] = bv1;
            __syncthreads();
            buf = nb;
        }
    }

#pragma unroll
    for (int ih = 0; ih < 2; ih++) {
#pragma unroll
        for (int i = 0; i < 4; i++) {
            const int r = rowBase + ih * 64 + ty * 4 + i;
#pragma unroll
            for (int jh = 0; jh < 2; jh++) {
                const int c = colBase + jh * 64 + tx * 4;
                const float4 bb = *(const float4*)&b3[c];
                float4 v;
                v.x = fmaxf(acc[ih * 4 + i][jh * 4 + 0] + bb.x, 0.f);
                v.y = fmaxf(acc[ih * 4 + i][jh * 4 + 1] + bb.y, 0.f);
                v.z = fmaxf(acc[ih * 4 + i][jh * 4 + 2] + bb.z, 0.f);
                v.w = fmaxf(acc[ih * 4 + i][jh * 4 + 3] + bb.w, 0.f);
                *(float4*)&out[(size_t)r * DD + c] = v;
            }
        }
    }
}

// ---------------------------------------------------------------------------
// Inputs (metadata order):
// 0 edge_pred[8192] f32 | 1 edge_corner[8192,2] i64 | 2 all_corners[4096,2] f32
// 3 edge_x[8192,256] f32 | 4 image_x[1024] f32 | 5 W1[256,256] | 6 b1[256]
// 7 W2[256,256] | 8 b2[256] | 9 W3[768,256] | 10 b3[256]
// Output: [8192, 256] f32
// ---------------------------------------------------------------------------
extern "C" void kernel_launch(void* const* d_in, const int* in_sizes, int n_in,
                              void* d_out, int out_size)
{
    (void)in_sizes; (void)n_in; (void)out_size;
    const float* X  = (const float*)d_in[3];
    const float* W1 = (const float*)d_in[5];
    const float* b1 = (const float*)d_in[6];
    const float* W2 = (const float*)d_in[7];
    const float* b2 = (const float*)d_in[8];
    const float* W3 = (const float*)d_in[9];
    const float* b3 = (const float*)d_in[10];
    float* out = (float*)d_out;

    k_e<<<dim3(2, 64, 2), 256>>>(X, W1, b1, W2, b2);
    k_mpart<<<dim3(2, 2, 2 * SPLITK), 256>>>(X);
    k_mreduce<<<512, 256>>>();
    k_p<<<dim3(4, 4, 2), 256>>>(W3);
    k_final<<<dim3(2, 64), 256>>>(X, W3, b3, out);
}

// round 3
// speedup vs baseline: 1.4062x; 1.0228x over previous
#include <cuda_runtime.h>

#define NEDGE 8192
#define DD    256
#define SPLITK 16

// Scratch (device globals; no allocation allowed)
__device__ float g_e[2][NEDGE][DD];            // e1, e2          (16 MB)
__device__ float g_Mpart[2][SPLITK][DD * DD];  // split-K partials (8 MB)
__device__ float g_M[2][DD * DD];              // M1, M2
__device__ float g_P[2][DD * DD];              // P1, P2

typedef unsigned long long u64;

// ---- packed fp32x2 helpers (sm_100+: FFMA2 reachable only via PTX) ----
__device__ __forceinline__ u64 pk2(float lo, float hi) {
    u64 r; asm("mov.b64 %0, {%1, %2};" : "=l"(r) : "f"(lo), "f"(hi)); return r;
}
__device__ __forceinline__ void upk2(float& lo, float& hi, u64 v) {
    asm("mov.b64 {%0, %1}, %2;" : "=f"(lo), "=f"(hi) : "l"(v));
}
__device__ __forceinline__ void fma2(u64& d, u64 a, u64 b) {
    asm("fma.rn.f32x2 %0, %1, %2, %0;" : "+l"(d) : "l"(a), "l"(b));
}

// ---- cp.async helpers ----
__device__ __forceinline__ void cpa16(void* dst, const void* src) {
    unsigned s = (unsigned)__cvta_generic_to_shared(dst);
    asm volatile("cp.async.cg.shared.global [%0], [%1], 16;" :: "r"(s), "l"(src));
}
__device__ __forceinline__ void cpa_commit() { asm volatile("cp.async.commit_group;"); }
__device__ __forceinline__ void cpa_wait0()  { asm volatile("cp.async.wait_group 0;"); }

// ===========================================================================
// Kernel 1: e_z = relu(X @ W_z + b_z). 128x128 tile, 8x8 micro (FFMA2 packed).
// A tile kept row-major [128][16] (pad 20) so cp.async needs no transpose;
// per-kk A reads are column scalars (ty-broadcast, conflict-free).
// grid (2, 64, 2), 256 threads.
// ===========================================================================
__global__ void __launch_bounds__(256, 2)
k_e(const float* __restrict__ X,
    const float* __restrict__ W1, const float* __restrict__ b1,
    const float* __restrict__ W2, const float* __restrict__ b2)
{
    const int z = blockIdx.z;
    const float* __restrict__ A = X;
    const float* __restrict__ B = z ? W2 : W1;
    const float* __restrict__ bias = z ? b2 : b1;
    float* __restrict__ C = &g_e[z][0][0];

    __shared__ __align__(16) float As[2][128][20];
    __shared__ __align__(16) float Bs[2][16][132];

    const int tid = threadIdx.x;
    const int tx = tid & 15;
    const int ty = tid >> 4;
    const int rowBase = blockIdx.y * 128;
    const int colBase = blockIdx.x * 128;

    // A tile: 128 rows x 16 k -> 512 16B chunks. chunk c: row=c>>2, off=(c&3)*4
    // B tile: 16 k x 128 cols -> 512 chunks. chunk c: row=c>>5, off=(c&31)*4
    const int ac0r = tid >> 2,        ac0o = (tid & 3) * 4;
    const int ac1r = (tid + 256) >> 2, ac1o = ((tid + 256) & 3) * 4;
    const int bc0r = tid >> 5,        bc0o = (tid & 31) * 4;
    const int bc1r = (tid + 256) >> 5, bc1o = ((tid + 256) & 31) * 4;

    u64 acc[8][4] = {};

    // prefetch tile 0
    cpa16(&As[0][ac0r][ac0o], &A[(size_t)(rowBase + ac0r) * DD + ac0o]);
    cpa16(&As[0][ac1r][ac1o], &A[(size_t)(rowBase + ac1r) * DD + ac1o]);
    cpa16(&Bs[0][bc0r][bc0o], &B[(size_t)bc0r * DD + colBase + bc0o]);
    cpa16(&Bs[0][bc1r][bc1o], &B[(size_t)bc1r * DD + colBase + bc1o]);
    cpa_commit();

    int buf = 0;
    for (int kt = 0; kt < DD; kt += 16) {
        cpa_wait0();
        __syncthreads();
        if (kt + 16 < DD) {
            const int nb = buf ^ 1;
            const int k2 = kt + 16;
            cpa16(&As[nb][ac0r][ac0o], &A[(size_t)(rowBase + ac0r) * DD + k2 + ac0o]);
            cpa16(&As[nb][ac1r][ac1o], &A[(size_t)(rowBase + ac1r) * DD + k2 + ac1o]);
            cpa16(&Bs[nb][bc0r][bc0o], &B[(size_t)(k2 + bc0r) * DD + colBase + bc0o]);
            cpa16(&Bs[nb][bc1r][bc1o], &B[(size_t)(k2 + bc1r) * DD + colBase + bc1o]);
            cpa_commit();
        }
#pragma unroll
        for (int kk = 0; kk < 16; kk++) {
            u64 a2[8], b2[4];
#pragma unroll
            for (int i = 0; i < 4; i++) {
                const float v = As[buf][ty * 4 + i][kk];
                const float w = As[buf][64 + ty * 4 + i][kk];
                a2[i] = pk2(v, v);
                a2[4 + i] = pk2(w, w);
            }
            const float4 q0 = *(const float4*)&Bs[buf][kk][tx * 4];
            const float4 q1 = *(const float4*)&Bs[buf][kk][64 + tx * 4];
            b2[0] = pk2(q0.x, q0.y); b2[1] = pk2(q0.z, q0.w);
            b2[2] = pk2(q1.x, q1.y); b2[3] = pk2(q1.z, q1.w);
#pragma unroll
            for (int i = 0; i < 8; i++)
#pragma unroll
                for (int j = 0; j < 4; j++)
                    fma2(acc[i][j], a2[i], b2[j]);
        }
        buf ^= 1;
    }

#pragma unroll
    for (int ih = 0; ih < 2; ih++) {
#pragma unroll
        for (int i = 0; i < 4; i++) {
            const int r = rowBase + ih * 64 + ty * 4 + i;
#pragma unroll
            for (int jh = 0; jh < 2; jh++) {
                const int c = colBase + jh * 64 + tx * 4;
                float4 v;
                upk2(v.x, v.y, acc[ih * 4 + i][jh * 2 + 0]);
                upk2(v.z, v.w, acc[ih * 4 + i][jh * 2 + 1]);
                const float4 bb = *(const float4*)&bias[c];
                v.x = fmaxf(v.x + bb.x, 0.f); v.y = fmaxf(v.y + bb.y, 0.f);
                v.z = fmaxf(v.z + bb.z, 0.f); v.w = fmaxf(v.w + bb.w, 0.f);
                *(float4*)&C[(size_t)r * DD + c] = v;
            }
        }
    }
}

// ===========================================================================
// Kernel 2: split-K partials of M_z = e_zᵀ @ X. Both operands k-major rows →
// both cp.async'd as [16][132] tiles, all reads vectorized. FFMA2 packed.
// grid (2, 2, 2*SPLITK), 256 threads.
// ===========================================================================
__global__ void __launch_bounds__(256, 2)
k_mpart(const float* __restrict__ X)
{
    const int mat = blockIdx.z >> 4;
    const int split = blockIdx.z & (SPLITK - 1);
    const float* __restrict__ E = &g_e[mat][0][0];
    float* __restrict__ Cp = &g_Mpart[mat][split][0];

    __shared__ __align__(16) float Es[2][16][132];
    __shared__ __align__(16) float Xs[2][16][132];

    const int tid = threadIdx.x;
    const int tx = tid & 15;
    const int ty = tid >> 4;
    const int kBase = blockIdx.y * 128;
    const int jBase = blockIdx.x * 128;

    const int c0r = tid >> 5,        c0o = (tid & 31) * 4;
    const int c1r = (tid + 256) >> 5, c1o = ((tid + 256) & 31) * 4;

    const int CHUNK = NEDGE / SPLITK;  // 512
    const int i0 = split * CHUNK;

    u64 acc[8][4] = {};

    cpa16(&Es[0][c0r][c0o], &E[(size_t)(i0 + c0r) * DD + kBase + c0o]);
    cpa16(&Es[0][c1r][c1o], &E[(size_t)(i0 + c1r) * DD + kBase + c1o]);
    cpa16(&Xs[0][c0r][c0o], &X[(size_t)(i0 + c0r) * DD + jBase + c0o]);
    cpa16(&Xs[0][c1r][c1o], &X[(size_t)(i0 + c1r) * DD + jBase + c1o]);
    cpa_commit();

    int buf = 0;
    for (int it = 0; it < CHUNK; it += 16) {
        cpa_wait0();
        __syncthreads();
        if (it + 16 < CHUNK) {
            const int nb = buf ^ 1;
            const int r2 = i0 + it + 16;
            cpa16(&Es[nb][c0r][c0o], &E[(size_t)(r2 + c0r) * DD + kBase + c0o]);
            cpa16(&Es[nb][c1r][c1o], &E[(size_t)(r2 + c1r) * DD + kBase + c1o]);
            cpa16(&Xs[nb][c0r][c0o], &X[(size_t)(r2 + c0r) * DD + jBase + c0o]);
            cpa16(&Xs[nb][c1r][c1o], &X[(size_t)(r2 + c1r) * DD + jBase + c1o]);
            cpa_commit();
        }
#pragma unroll
        for (int kk = 0; kk < 16; kk++) {
            const float4 a0 = *(const float4*)&Es[buf][kk][ty * 4];
            const float4 a1 = *(const float4*)&Es[buf][kk][64 + ty * 4];
            const float4 q0 = *(const float4*)&Xs[buf][kk][tx * 4];
            const float4 q1 = *(const float4*)&Xs[buf][kk][64 + tx * 4];
            u64 a2[8], b2[4];
            a2[0] = pk2(a0.x, a0.x); a2[1] = pk2(a0.y, a0.y);
            a2[2] = pk2(a0.z, a0.z); a2[3] = pk2(a0.w, a0.w);
            a2[4] = pk2(a1.x, a1.x); a2[5] = pk2(a1.y, a1.y);
            a2[6] = pk2(a1.z, a1.z); a2[7] = pk2(a1.w, a1.w);
            b2[0] = pk2(q0.x, q0.y); b2[1] = pk2(q0.z, q0.w);
            b2[2] = pk2(q1.x, q1.y); b2[3] = pk2(q1.z, q1.w);
#pragma unroll
            for (int i = 0; i < 8; i++)
#pragma unroll
                for (int j = 0; j < 4; j++)
                    fma2(acc[i][j], a2[i], b2[j]);
        }
        buf ^= 1;
    }

#pragma unroll
    for (int ih = 0; ih < 2; ih++) {
#pragma unroll
        for (int i = 0; i < 4; i++) {
            const int r = kBase + ih * 64 + ty * 4 + i;
#pragma unroll
            for (int jh = 0; jh < 2; jh++) {
                const int c = jBase + jh * 64 + tx * 4;
                float4 v;
                upk2(v.x, v.y, acc[ih * 4 + i][jh * 2 + 0]);
                upk2(v.z, v.w, acc[ih * 4 + i][jh * 2 + 1]);
                *(float4*)&Cp[(size_t)r * DD + c] = v;
            }
        }
    }
}

// ===========================================================================
// Kernel 3: deterministic reduce of split-K partials, scale by 1/D.
// ===========================================================================
__global__ void k_mreduce()
{
    const int idx = blockIdx.x * 256 + threadIdx.x;
    const int mat = idx >> 16;
    const int o = idx & 0xFFFF;
    float s = 0.f;
#pragma unroll
    for (int p = 0; p < SPLITK; p++) s += g_Mpart[mat][p][o];
    g_M[mat][o] = s * (1.0f / DD);
}

// ===========================================================================
// Kernel 4: P_z = M_z @ W3[(1+z)*256:(2+z)*256]. 32x32 tiles -> grid
// (8,8,2)=128 blocks (latency fix), cp.async double-buffered, 2x2 micro.
// ===========================================================================
__global__ void __launch_bounds__(256, 2)
k_p(const float* __restrict__ W3)
{
    const int z = blockIdx.z;
    const float* __restrict__ A = g_M[z];
    const float* __restrict__ B = W3 + (size_t)(DD + z * DD) * DD;
    float* __restrict__ C = g_P[z];

    __shared__ __align__(16) float As[2][32][20];  // 32 rows x 16 k
    __shared__ __align__(16) float Bs[2][16][36];  // 16 k x 32 cols

    const int tid = threadIdx.x;
    const int tx = tid & 15;
    const int ty = tid >> 4;
    const int rowBase = blockIdx.y * 32;
    const int colBase = blockIdx.x * 32;

    // A: 32x16 = 128 chunks (threads 0..127). chunk c: row=c>>2, off=(c&3)*4
    // B: 16x32 = 128 chunks (threads 128..255). chunk c: row=c>>3, off=(c&7)*4
    const bool isA = tid < 128;
    const int cc = isA ? tid : tid - 128;
    const int ar = cc >> 2, ao = (cc & 3) * 4;
    const int br = cc >> 3, bo = (cc & 7) * 4;

    float a00 = 0.f, a01 = 0.f, a10 = 0.f, a11 = 0.f;

    if (isA) cpa16(&As[0][ar][ao], &A[(size_t)(rowBase + ar) * DD + ao]);
    else     cpa16(&Bs[0][br][bo], &B[(size_t)br * DD + colBase + bo]);
    cpa_commit();

    int buf = 0;
    for (int kt = 0; kt < DD; kt += 16) {
        cpa_wait0();
        __syncthreads();
        if (kt + 16 < DD) {
            const int nb = buf ^ 1;
            const int k2 = kt + 16;
            if (isA) cpa16(&As[nb][ar][ao], &A[(size_t)(rowBase + ar) * DD + k2 + ao]);
            else     cpa16(&Bs[nb][br][bo], &B[(size_t)(k2 + br) * DD + colBase + bo]);
            cpa_commit();
        }
#pragma unroll
        for (int kk = 0; kk < 16; kk++) {
            const float av0 = As[buf][ty * 2 + 0][kk];
            const float av1 = As[buf][ty * 2 + 1][kk];
            const float2 bv = *(const float2*)&Bs[buf][kk][tx * 2];
            a00 = fmaf(av0, bv.x, a00); a01 = fmaf(av0, bv.y, a01);
            a10 = fmaf(av1, bv.x, a10); a11 = fmaf(av1, bv.y, a11);
        }
        buf ^= 1;
    }

    const int r0 = rowBase + ty * 2;
    const int c0 = colBase + tx * 2;
    *(float2*)&C[(size_t)(r0 + 0) * DD + c0] = make_float2(a00, a01);
    *(float2*)&C[(size_t)(r0 + 1) * DD + c0] = make_float2(a10, a11);
}

// ===========================================================================
// Kernel 5: out = relu(X@W3a + e1@P1 + e2@P2 + b3) as K=768 GEMM with
// per-256-chunk source selection. FFMA2 + cp.async. grid (2, 64).
// ===========================================================================
__global__ void __launch_bounds__(256, 2)
k_final(const float* __restrict__ X,
        const float* __restrict__ W3, const float* __restrict__ b3,
        float* __restrict__ out)
{
    __shared__ __align__(16) float As[2][128][20];
    __shared__ __align__(16) float Bs[2][16][132];

    const float* __restrict__ Asrc[3] = {X, &g_e[0][0][0], &g_e[1][0][0]};
    const float* __restrict__ Bsrc[3] = {W3, g_P[0], g_P[1]};

    const int tid = threadIdx.x;
    const int tx = tid & 15;
    const int ty = tid >> 4;
    const int rowBase = blockIdx.y * 128;
    const int colBase = blockIdx.x * 128;

    const int ac0r = tid >> 2,        ac0o = (tid & 3) * 4;
    const int ac1r = (tid + 256) >> 2, ac1o = ((tid + 256) & 3) * 4;
    const int bc0r = tid >> 5,        bc0o = (tid & 31) * 4;
    const int bc1r = (tid + 256) >> 5, bc1o = ((tid + 256) & 31) * 4;

    u64 acc[8][4] = {};

    cpa16(&As[0][ac0r][ac0o], &Asrc[0][(size_t)(rowBase + ac0r) * DD + ac0o]);
    cpa16(&As[0][ac1r][ac1o], &Asrc[0][(size_t)(rowBase + ac1r) * DD + ac1o]);
    cpa16(&Bs[0][bc0r][bc0o], &Bsrc[0][(size_t)bc0r * DD + colBase + bc0o]);
    cpa16(&Bs[0][bc1r][bc1o], &Bsrc[0][(size_t)bc1r * DD + colBase + bc1o]);
    cpa_commit();

    int buf = 0;
    for (int kt = 0; kt < 768; kt += 16) {
        cpa_wait0();
        __syncthreads();
        if (kt + 16 < 768) {
            const int nb = buf ^ 1;
            const int k2 = kt + 16;
            const int src = k2 >> 8;
            const int kc = k2 & 255;
            const float* __restrict__ A = Asrc[src];
            const float* __restrict__ B = Bsrc[src];
            cpa16(&As[nb][ac0r][ac0o], &A[(size_t)(rowBase + ac0r) * DD + kc + ac0o]);
            cpa16(&As[nb][ac1r][ac1o], &A[(size_t)(rowBase + ac1r) * DD + kc + ac1o]);
            cpa16(&Bs[nb][bc0r][bc0o], &B[(size_t)(kc + bc0r) * DD + colBase + bc0o]);
            cpa16(&Bs[nb][bc1r][bc1o], &B[(size_t)(kc + bc1r) * DD + colBase + bc1o]);
            cpa_commit();
        }
#pragma unroll
        for (int kk = 0; kk < 16; kk++) {
            u64 a2[8], b2[4];
#pragma unroll
            for (int i = 0; i < 4; i++) {
                const float v = As[buf][ty * 4 + i][kk];
                const float w = As[buf][64 + ty * 4 + i][kk];
                a2[i] = pk2(v, v);
                a2[4 + i] = pk2(w, w);
            }
            const float4 q0 = *(const float4*)&Bs[buf][kk][tx * 4];
            const float4 q1 = *(const float4*)&Bs[buf][kk][64 + tx * 4];
            b2[0] = pk2(q0.x, q0.y); b2[1] = pk2(q0.z, q0.w);
            b2[2] = pk2(q1.x, q1.y); b2[3] = pk2(q1.z, q1.w);
#pragma unroll
            for (int i = 0; i < 8; i++)
#pragma unroll
                for (int j = 0; j < 4; j++)
                    fma2(acc[i][j], a2[i], b2[j]);
        }
        buf ^= 1;
    }

#pragma unroll
    for (int ih = 0; ih < 2; ih++) {
#pragma unroll
        for (int i = 0; i < 4; i++) {
            const int r = rowBase + ih * 64 + ty * 4 + i;
#pragma unroll
            for (int jh = 0; jh < 2; jh++) {
                const int c = colBase + jh * 64 + tx * 4;
                float4 v;
                upk2(v.x, v.y, acc[ih * 4 + i][jh * 2 + 0]);
                upk2(v.z, v.w, acc[ih * 4 + i][jh * 2 + 1]);
                const float4 bb = *(const float4*)&b3[c];
                v.x = fmaxf(v.x + bb.x, 0.f); v.y = fmaxf(v.y + bb.y, 0.f);
                v.z = fmaxf(v.z + bb.z, 0.f); v.w = fmaxf(v.w + bb.w, 0.f);
                *(float4*)&out[(size_t)r * DD + c] = v;
            }
        }
    }
}

// ---------------------------------------------------------------------------
// Inputs (metadata order):
// 0 edge_pred[8192] f32 | 1 edge_corner[8192,2] i64 | 2 all_corners[4096,2] f32
// 3 edge_x[8192,256] f32 | 4 image_x[1024] f32 | 5 W1[256,256] | 6 b1[256]
// 7 W2[256,256] | 8 b2[256] | 9 W3[768,256] | 10 b3[256]
// Output: [8192, 256] f32
// ---------------------------------------------------------------------------
extern "C" void kernel_launch(void* const* d_in, const int* in_sizes, int n_in,
                              void* d_out, int out_size)
{
    (void)in_sizes; (void)n_in; (void)out_size;
    const float* X  = (const float*)d_in[3];
    const float* W1 = (const float*)d_in[5];
    const float* b1 = (const float*)d_in[6];
    const float* W2 = (const float*)d_in[7];
    const float* b2 = (const float*)d_in[8];
    const float* W3 = (const float*)d_in[9];
    const float* b3 = (const float*)d_in[10];
    float* out = (float*)d_out;

    k_e<<<dim3(2, 64, 2), 256>>>(X, W1, b1, W2, b2);
    k_mpart<<<dim3(2, 2, 2 * SPLITK), 256>>>(X);
    k_mreduce<<<512, 256>>>();
    k_p<<<dim3(8, 8, 2), 256>>>(W3);
    k_final<<<dim3(2, 64), 256>>>(X, W3, b3, out);
}

// round 4
// speedup vs baseline: 2.1546x; 1.5322x over previous
#include <cuda_runtime.h>
#include <cuda_bf16.h>

#define NEDGE 8192
#define DD    256
#define SPLITK 16

typedef __nv_bfloat16 bf16;
typedef unsigned int u32;

// ---------------- scratch (device globals; no allocation allowed) ----------
__device__ __align__(16) bf16 g_Xh[NEDGE * DD], g_Xl[NEDGE * DD];
__device__ __align__(16) bf16 g_eh[2][NEDGE * DD], g_el[2][NEDGE * DD];
__device__ __align__(16) bf16 g_W1h[DD * DD], g_W1l[DD * DD];
__device__ __align__(16) bf16 g_W2h[DD * DD], g_W2l[DD * DD];
__device__ __align__(16) bf16 g_W3ah[DD * DD], g_W3al[DD * DD];
__device__ __align__(16) bf16 g_Ph[2][DD * DD], g_Pl[2][DD * DD];
__device__ float g_Mpart[2][SPLITK][DD * DD];
__device__ float g_M[2][DD * DD];
__device__ float g_Ppart[2][4][DD * DD];

// ---------------- helpers ---------------------------------------------------
__device__ __forceinline__ void cpa16(void* dst, const void* src) {
    unsigned s = (unsigned)__cvta_generic_to_shared(dst);
    asm volatile("cp.async.cg.shared.global [%0], [%1], 16;" :: "r"(s), "l"(src));
}
__device__ __forceinline__ void cpa_commit() { asm volatile("cp.async.commit_group;"); }
__device__ __forceinline__ void cpa_wait0()  { asm volatile("cp.async.wait_group 0;"); }

__device__ __forceinline__ unsigned saddr(const void* p) {
    return (unsigned)__cvta_generic_to_shared(p);
}
__device__ __forceinline__ void ldsm_x4(u32* r, unsigned a) {
    asm volatile("ldmatrix.sync.aligned.m8n8.x4.shared.b16 {%0,%1,%2,%3}, [%4];"
        : "=r"(r[0]), "=r"(r[1]), "=r"(r[2]), "=r"(r[3]) : "r"(a));
}
__device__ __forceinline__ void ldsm_x4_t(u32* r, unsigned a) {
    asm volatile("ldmatrix.sync.aligned.m8n8.x4.trans.shared.b16 {%0,%1,%2,%3}, [%4];"
        : "=r"(r[0]), "=r"(r[1]), "=r"(r[2]), "=r"(r[3]) : "r"(a));
}
__device__ __forceinline__ void ldsm_x2_t(u32* r, unsigned a) {
    asm volatile("ldmatrix.sync.aligned.m8n8.x2.trans.shared.b16 {%0,%1}, [%2];"
        : "=r"(r[0]), "=r"(r[1]) : "r"(a));
}
__device__ __forceinline__ void mma_bf16(float* d, const u32* a, const u32* b) {
    asm volatile(
        "mma.sync.aligned.m16n8k16.row.col.f32.bf16.bf16.f32 "
        "{%0,%1,%2,%3}, {%4,%5,%6,%7}, {%8,%9}, {%0,%1,%2,%3};"
        : "+f"(d[0]), "+f"(d[1]), "+f"(d[2]), "+f"(d[3])
        : "r"(a[0]), "r"(a[1]), "r"(a[2]), "r"(a[3]), "r"(b[0]), "r"(b[1]));
}
__device__ __forceinline__ void split_store(bf16* Hp, bf16* Lp, size_t off,
                                            float v0, float v1) {
    bf16 h0 = __float2bfloat16(v0), h1 = __float2bfloat16(v1);
    bf16 l0 = __float2bfloat16(v0 - __bfloat162float(h0));
    bf16 l1 = __float2bfloat16(v1 - __bfloat162float(h1));
    __nv_bfloat162 H; H.x = h0; H.y = h1;
    __nv_bfloat162 L; L.x = l0; L.y = l1;
    *reinterpret_cast<__nv_bfloat162*>(Hp + off) = H;
    *reinterpret_cast<__nv_bfloat162*>(Lp + off) = L;
}

// ===========================================================================
// Convert inputs to bf16 hi/lo: X (2,097,152 elems) + W1,W2,W3a (3*65,536).
// grid 8960 x 256 (exact).
// ===========================================================================
__global__ void k_cvt(const float* __restrict__ X, const float* __restrict__ W1,
                      const float* __restrict__ W2, const float* __restrict__ W3)
{
    const int idx = blockIdx.x * 256 + threadIdx.x;
    if (idx < NEDGE * DD) {
        const float v = X[idx];
        const bf16 h = __float2bfloat16(v);
        g_Xh[idx] = h;
        g_Xl[idx] = __float2bfloat16(v - __bfloat162float(h));
    } else {
        const int w = idx - NEDGE * DD;
        const int which = w >> 16;
        const int off = w & 65535;
        const float* S = (which == 0) ? W1 : (which == 1) ? W2 : W3;  // W3 rows 0-255 = W3a
        bf16* Hd = (which == 0) ? g_W1h : (which == 1) ? g_W2h : g_W3ah;
        bf16* Ld = (which == 0) ? g_W1l : (which == 1) ? g_W2l : g_W3al;
        const float v = S[off];
        const bf16 h = __float2bfloat16(v);
        Hd[off] = h;
        Ld[off] = __float2bfloat16(v - __bfloat162float(h));
    }
}

// ===========================================================================
// Core: multi-pass bf16 MMA GEMM, A row-major [M][256], B row-major [256][N].
// Block tile 128x128, 8 warps as 2(m) x 4(n), warp tile 64x32.
// k-tile = 32, cp.async double-buffered, NPASS passes of K=256 each.
// ===========================================================================
template <int NPASS>
__device__ __forceinline__ void mma_core_rowA(
    const bf16* const* Ap, const bf16* const* Bp,
    int rowBase, int colBase, float (&acc)[4][4][4])
{
    __shared__ __align__(16) bf16 As[2][128][40];
    __shared__ __align__(16) bf16 Bs[2][32][136];

    const int tid = threadIdx.x;
    const int lane = tid & 31, w = tid >> 5;
    const int m0w = (w >> 2) * 64, n0w = (w & 3) * 32;

    const int a0r = tid >> 2,  a0o = (tid & 3) * 8;   // A: 128 rows x 32k, 16B chunks
    const int a1r = a0r + 64;
    const int b0r = tid >> 4,  b0o = (tid & 15) * 8;  // B: 32k x 128n
    const int b1r = b0r + 16;

    auto prefetch = [&](int it, int bufn) {
        const int pass = it >> 3;
        const int k0 = (it & 7) * 32;
        const bf16* __restrict__ A = Ap[pass];
        const bf16* __restrict__ B = Bp[pass];
        cpa16(&As[bufn][a0r][a0o], A + (size_t)(rowBase + a0r) * DD + k0 + a0o);
        cpa16(&As[bufn][a1r][a0o], A + (size_t)(rowBase + a1r) * DD + k0 + a0o);
        cpa16(&Bs[bufn][b0r][b0o], B + (size_t)(k0 + b0r) * DD + colBase + b0o);
        cpa16(&Bs[bufn][b1r][b0o], B + (size_t)(k0 + b1r) * DD + colBase + b0o);
        cpa_commit();
    };

    const int t = lane >> 3;
    const int aro = (t & 1) * 8 + (lane & 7);  // A ldmatrix row offset
    const int aco = (t >> 1) * 8;              // A ldmatrix col offset
    const int bro = lane & 15;                 // B ldmatrix row offset

    prefetch(0, 0);
    int buf = 0;
    const int NIT = NPASS * 8;
    for (int it = 0; it < NIT; ++it) {
        cpa_wait0();
        __syncthreads();
        if (it + 1 < NIT) prefetch(it + 1, buf ^ 1);
#pragma unroll
        for (int ki = 0; ki < 2; ++ki) {
            u32 a[4][4], b[4][2];
#pragma unroll
            for (int mi = 0; mi < 4; ++mi)
                ldsm_x4(a[mi], saddr(&As[buf][m0w + mi * 16 + aro][ki * 16 + aco]));
#pragma unroll
            for (int ni = 0; ni < 4; ++ni)
                ldsm_x2_t(b[ni], saddr(&Bs[buf][ki * 16 + bro][n0w + ni * 8]));
#pragma unroll
            for (int mi = 0; mi < 4; ++mi)
#pragma unroll
                for (int ni = 0; ni < 4; ++ni)
                    mma_bf16(acc[mi][ni], a[mi], b[ni]);
        }
        __syncthreads();
        buf ^= 1;
    }
}

// ===========================================================================
// Kernel: e_z = relu(X @ W_z + b_z), emitted as bf16 hi/lo. grid (2,64,2).
// ===========================================================================
__global__ void k_e_mma(const float* __restrict__ b1, const float* __restrict__ b2)
{
    const int z = blockIdx.z;
    const bf16* Ap[3] = {g_Xh, g_Xh, g_Xl};
    const bf16* Bp[3] = {z ? g_W2h : g_W1h, z ? g_W2l : g_W1l, z ? g_W2h : g_W1h};
    const float* __restrict__ bias = z ? b2 : b1;
    bf16* __restrict__ Eh = g_eh[z];
    bf16* __restrict__ El = g_el[z];

    const int rowBase = blockIdx.y * 128, colBase = blockIdx.x * 128;
    float acc[4][4][4] = {};
    mma_core_rowA<3>(Ap, Bp, rowBase, colBase, acc);

    const int lane = threadIdx.x & 31, w = threadIdx.x >> 5;
    const int m0w = (w >> 2) * 64, n0w = (w & 3) * 32;
    const int r_l = lane >> 2, c_l = (lane & 3) * 2;
#pragma unroll
    for (int mi = 0; mi < 4; ++mi)
#pragma unroll
        for (int ni = 0; ni < 4; ++ni) {
            const int col = colBase + n0w + ni * 8 + c_l;
            const float2 bb = *(const float2*)&bias[col];
#pragma unroll
            for (int h = 0; h < 2; ++h) {
                const int r = rowBase + m0w + mi * 16 + r_l + h * 8;
                float v0 = fmaxf(acc[mi][ni][h * 2 + 0] + bb.x, 0.f);
                float v1 = fmaxf(acc[mi][ni][h * 2 + 1] + bb.y, 0.f);
                split_store(Eh, El, (size_t)r * DD + col, v0, v1);
            }
        }
}

// ===========================================================================
// Kernel: split-K partials of M_z = e_zᵀ @ X (A = e^T via ldmatrix.trans).
// grid (2, 2, 2*16), block tile 128x128, edge-chunk 512 per split.
// ===========================================================================
__global__ void k_mpart_mma()
{
    const int mat = blockIdx.z >> 4, split = blockIdx.z & 15;
    const bf16* Ap[3] = {g_eh[mat], g_eh[mat], g_el[mat]};
    const bf16* Bp[3] = {g_Xh, g_Xl, g_Xh};
    float* __restrict__ Cp = g_Mpart[mat][split];

    __shared__ __align__(16) bf16 Es[2][32][136];
    __shared__ __align__(16) bf16 Xs[2][32][136];

    const int tid = threadIdx.x;
    const int lane = tid & 31, w = tid >> 5;
    const int m0w = (w >> 2) * 64, n0w = (w & 3) * 32;
    const int mBase = blockIdx.y * 128, nBase = blockIdx.x * 128;
    const int i0 = split * (NEDGE / SPLITK);

    const int c0r = tid >> 4, c0o = (tid & 15) * 8;
    const int c1r = c0r + 16;

    auto prefetch = [&](int it, int bufn) {
        const int pass = it >> 4;
        const int e0 = i0 + (it & 15) * 32;
        const bf16* __restrict__ E = Ap[pass];
        const bf16* __restrict__ X = Bp[pass];
        cpa16(&Es[bufn][c0r][c0o], E + (size_t)(e0 + c0r) * DD + mBase + c0o);
        cpa16(&Es[bufn][c1r][c0o], E + (size_t)(e0 + c1r) * DD + mBase + c0o);
        cpa16(&Xs[bufn][c0r][c0o], X + (size_t)(e0 + c0r) * DD + nBase + c0o);
        cpa16(&Xs[bufn][c1r][c0o], X + (size_t)(e0 + c1r) * DD + nBase + c0o);
        cpa_commit();
    };

    const int t = lane >> 3;
    const int akro = (t >> 1) * 8 + (lane & 7);  // trans-A: k row offset
    const int amco = (t & 1) * 8;                // trans-A: m col offset
    const int bro = lane & 15;

    float acc[4][4][4] = {};
    prefetch(0, 0);
    int buf = 0;
    for (int it = 0; it < 48; ++it) {
        cpa_wait0();
        __syncthreads();
        if (it + 1 < 48) prefetch(it + 1, buf ^ 1);
#pragma unroll
        for (int ki = 0; ki < 2; ++ki) {
            u32 a[4][4], b[4][2];
#pragma unroll
            for (int mi = 0; mi < 4; ++mi)
                ldsm_x4_t(a[mi], saddr(&Es[buf][ki * 16 + akro][m0w + mi * 16 + amco]));
#pragma unroll
            for (int ni = 0; ni < 4; ++ni)
                ldsm_x2_t(b[ni], saddr(&Xs[buf][ki * 16 + bro][n0w + ni * 8]));
#pragma unroll
            for (int mi = 0; mi < 4; ++mi)
#pragma unroll
                for (int ni = 0; ni < 4; ++ni)
                    mma_bf16(acc[mi][ni], a[mi], b[ni]);
        }
        __syncthreads();
        buf ^= 1;
    }

    const int r_l = lane >> 2, c_l = (lane & 3) * 2;
#pragma unroll
    for (int mi = 0; mi < 4; ++mi)
#pragma unroll
        for (int ni = 0; ni < 4; ++ni) {
            const int col = nBase + n0w + ni * 8 + c_l;
#pragma unroll
            for (int h = 0; h < 2; ++h) {
                const int r = mBase + m0w + mi * 16 + r_l + h * 8;
                float2 v = make_float2(acc[mi][ni][h * 2 + 0], acc[mi][ni][h * 2 + 1]);
                *(float2*)&Cp[(size_t)r * DD + col] = v;
            }
        }
}

// ===========================================================================
// Reduce split-K partials of M, scale by 1/D. grid 512 x 256.
// ===========================================================================
__global__ void k_mreduce()
{
    const int idx = blockIdx.x * 256 + threadIdx.x;
    const int mat = idx >> 16;
    const int o = idx & 0xFFFF;
    float s = 0.f;
#pragma unroll
    for (int p = 0; p < SPLITK; p++) s += g_Mpart[mat][p][o];
    g_M[mat][o] = s * (1.0f / DD);
}

// ===========================================================================
// P partials: P_z = M_z @ W3b_z, split-K x4. 32x32 out tile, K=64 per block.
// grid (8, 8, 2*4) = 512 blocks, fp32.
// ===========================================================================
__global__ void k_p(const float* __restrict__ W3)
{
    const int mat = blockIdx.z >> 2, ks = blockIdx.z & 3;
    const float* __restrict__ A = g_M[mat];
    const float* __restrict__ B = W3 + (size_t)(DD + mat * DD) * DD;
    float* __restrict__ Cp = g_Ppart[mat][ks];

    __shared__ __align__(16) float As[32][68];
    __shared__ __align__(16) float Bs[64][36];

    const int tid = threadIdx.x;
    const int mBase = blockIdx.y * 32, nBase = blockIdx.x * 32, k0 = ks * 64;

    {
        const int c0 = tid, c1 = tid + 256;
        cpa16(&As[c0 >> 4][(c0 & 15) * 4], &A[(size_t)(mBase + (c0 >> 4)) * DD + k0 + (c0 & 15) * 4]);
        cpa16(&As[c1 >> 4][(c1 & 15) * 4], &A[(size_t)(mBase + (c1 >> 4)) * DD + k0 + (c1 & 15) * 4]);
        cpa16(&Bs[c0 >> 3][(c0 & 7) * 4], &B[(size_t)(k0 + (c0 >> 3)) * DD + nBase + (c0 & 7) * 4]);
        cpa16(&Bs[c1 >> 3][(c1 & 7) * 4], &B[(size_t)(k0 + (c1 >> 3)) * DD + nBase + (c1 & 7) * 4]);
        cpa_commit(); cpa_wait0();
        __syncthreads();
    }

    const int ty = tid >> 4, tx = tid & 15;
    float a00 = 0.f, a01 = 0.f, a10 = 0.f, a11 = 0.f;
#pragma unroll
    for (int kk = 0; kk < 64; kk++) {
        const float av0 = As[ty * 2 + 0][kk];
        const float av1 = As[ty * 2 + 1][kk];
        const float2 bv = *(const float2*)&Bs[kk][tx * 2];
        a00 = fmaf(av0, bv.x, a00); a01 = fmaf(av0, bv.y, a01);
        a10 = fmaf(av1, bv.x, a10); a11 = fmaf(av1, bv.y, a11);
    }
    *(float2*)&Cp[(size_t)(mBase + ty * 2 + 0) * DD + nBase + tx * 2] = make_float2(a00, a01);
    *(float2*)&Cp[(size_t)(mBase + ty * 2 + 1) * DD + nBase + tx * 2] = make_float2(a10, a11);
}

// ===========================================================================
// Reduce P partials (fixed order) and convert to bf16 hi/lo. grid 512 x 256.
// ===========================================================================
__global__ void k_pcvt()
{
    const int idx = blockIdx.x * 256 + threadIdx.x;
    const int mat = idx >> 16;
    const int o = idx & 0xFFFF;
    float s = g_Ppart[mat][0][o] + g_Ppart[mat][1][o]
            + g_Ppart[mat][2][o] + g_Ppart[mat][3][o];
    const bf16 h = __float2bfloat16(s);
    g_Ph[mat][o] = h;
    g_Pl[mat][o] = __float2bfloat16(s - __bfloat162float(h));
}

// ===========================================================================
// Final: out = relu(X@W3a + e1@P1 + e2@P2 + b3). 9 bf16-split passes.
// grid (2, 64).
// ===========================================================================
__global__ void k_final_mma(const float* __restrict__ b3, float* __restrict__ out)
{
    const bf16* Ap[9] = {g_Xh, g_Xh, g_Xl,
                         g_eh[0], g_eh[0], g_el[0],
                         g_eh[1], g_eh[1], g_el[1]};
    const bf16* Bp[9] = {g_W3ah, g_W3al, g_W3ah,
                         g_Ph[0], g_Pl[0], g_Ph[0],
                         g_Ph[1], g_Pl[1], g_Ph[1]};

    const int rowBase = blockIdx.y * 128, colBase = blockIdx.x * 128;
    float acc[4][4][4] = {};
    mma_core_rowA<9>(Ap, Bp, rowBase, colBase, acc);

    const int lane = threadIdx.x & 31, w = threadIdx.x >> 5;
    const int m0w = (w >> 2) * 64, n0w = (w & 3) * 32;
    const int r_l = lane >> 2, c_l = (lane & 3) * 2;
#pragma unroll
    for (int mi = 0; mi < 4; ++mi)
#pragma unroll
        for (int ni = 0; ni < 4; ++ni) {
            const int col = colBase + n0w + ni * 8 + c_l;
            const float2 bb = *(const float2*)&b3[col];
#pragma unroll
            for (int h = 0; h < 2; ++h) {
                const int r = rowBase + m0w + mi * 16 + r_l + h * 8;
                float2 v;
                v.x = fmaxf(acc[mi][ni][h * 2 + 0] + bb.x, 0.f);
                v.y = fmaxf(acc[mi][ni][h * 2 + 1] + bb.y, 0.f);
                *(float2*)&out[(size_t)r * DD + col] = v;
            }
        }
}

// ---------------------------------------------------------------------------
// Inputs (metadata order):
// 0 edge_pred[8192] f32 | 1 edge_corner[8192,2] i64 | 2 all_corners[4096,2] f32
// 3 edge_x[8192,256] f32 | 4 image_x[1024] f32 | 5 W1[256,256] | 6 b1[256]
// 7 W2[256,256] | 8 b2[256] | 9 W3[768,256] | 10 b3[256]
// Output: [8192, 256] f32
// ---------------------------------------------------------------------------
extern "C" void kernel_launch(void* const* d_in, const int* in_sizes, int n_in,
                              void* d_out, int out_size)
{
    (void)in_sizes; (void)n_in; (void)out_size;
    const float* X  = (const float*)d_in[3];
    const float* W1 = (const float*)d_in[5];
    const float* b1 = (const float*)d_in[6];
    const float* W2 = (const float*)d_in[7];
    const float* b2 = (const float*)d_in[8];
    const float* W3 = (const float*)d_in[9];
    const float* b3 = (const float*)d_in[10];
    float* out = (float*)d_out;

    k_cvt<<<8960, 256>>>(X, W1, W2, W3);
    k_e_mma<<<dim3(2, 64, 2), 256>>>(b1, b2);
    k_mpart_mma<<<dim3(2, 2, 32), 256>>>();
    k_mreduce<<<512, 256>>>();
    k_p<<<dim3(8, 8, 8), 256>>>(W3);
    k_pcvt<<<512, 256>>>();
    k_final_mma<<<dim3(2, 64), 256>>>(b3, out);
}

// round 6
// speedup vs baseline: 2.1897x; 1.0163x over previous
#include <cuda_runtime.h>
#include <cuda_bf16.h>

#define NEDGE 8192
#define DD    256
#define SPLITK 16

typedef __nv_bfloat16 bf16;
typedef unsigned int u32;

// ---------------- scratch (device globals; no allocation allowed) ----------
__device__ __align__(16) bf16 g_Xh[NEDGE * DD], g_Xl[NEDGE * DD];
__device__ __align__(16) bf16 g_eh[2][NEDGE * DD], g_el[2][NEDGE * DD];
__device__ __align__(16) bf16 g_W1h[DD * DD], g_W1l[DD * DD];
__device__ __align__(16) bf16 g_W2h[DD * DD], g_W2l[DD * DD];
__device__ __align__(16) bf16 g_W3ah[DD * DD], g_W3al[DD * DD];
__device__ __align__(16) bf16 g_Ph[2][DD * DD], g_Pl[2][DD * DD];
__device__ float g_Mpart[2][SPLITK][DD * DD];
__device__ float g_M[2][DD * DD];
__device__ float g_Ppart[2][4][DD * DD];

// ---------------- helpers ---------------------------------------------------
__device__ __forceinline__ void cpa16(void* dst, const void* src) {
    unsigned s = (unsigned)__cvta_generic_to_shared(dst);
    asm volatile("cp.async.cg.shared.global [%0], [%1], 16;" :: "r"(s), "l"(src));
}
__device__ __forceinline__ void cpa_commit() { asm volatile("cp.async.commit_group;"); }
__device__ __forceinline__ void cpa_wait0()  { asm volatile("cp.async.wait_group 0;"); }
__device__ __forceinline__ void cpa_wait1()  { asm volatile("cp.async.wait_group 1;"); }

__device__ __forceinline__ unsigned saddr(const void* p) {
    return (unsigned)__cvta_generic_to_shared(p);
}
__device__ __forceinline__ void ldsm_x4(u32* r, unsigned a) {
    asm volatile("ldmatrix.sync.aligned.m8n8.x4.shared.b16 {%0,%1,%2,%3}, [%4];"
        : "=r"(r[0]), "=r"(r[1]), "=r"(r[2]), "=r"(r[3]) : "r"(a));
}
__device__ __forceinline__ void ldsm_x4_t(u32* r, unsigned a) {
    asm volatile("ldmatrix.sync.aligned.m8n8.x4.trans.shared.b16 {%0,%1,%2,%3}, [%4];"
        : "=r"(r[0]), "=r"(r[1]), "=r"(r[2]), "=r"(r[3]) : "r"(a));
}
__device__ __forceinline__ void ldsm_x2_t(u32* r, unsigned a) {
    asm volatile("ldmatrix.sync.aligned.m8n8.x2.trans.shared.b16 {%0,%1}, [%2];"
        : "=r"(r[0]), "=r"(r[1]) : "r"(a));
}
__device__ __forceinline__ void mma_bf16(float* d, const u32* a, const u32* b) {
    asm volatile(
        "mma.sync.aligned.m16n8k16.row.col.f32.bf16.bf16.f32 "
        "{%0,%1,%2,%3}, {%4,%5,%6,%7}, {%8,%9}, {%0,%1,%2,%3};"
        : "+f"(d[0]), "+f"(d[1]), "+f"(d[2]), "+f"(d[3])
        : "r"(a[0]), "r"(a[1]), "r"(a[2]), "r"(a[3]), "r"(b[0]), "r"(b[1]));
}
__device__ __forceinline__ void split_store(bf16* Hp, bf16* Lp, size_t off,
                                            float v0, float v1) {
    bf16 h0 = __float2bfloat16(v0), h1 = __float2bfloat16(v1);
    bf16 l0 = __float2bfloat16(v0 - __bfloat162float(h0));
    bf16 l1 = __float2bfloat16(v1 - __bfloat162float(h1));
    __nv_bfloat162 H; H.x = h0; H.y = h1;
    __nv_bfloat162 L; L.x = l0; L.y = l1;
    *reinterpret_cast<__nv_bfloat162*>(Hp + off) = H;
    *reinterpret_cast<__nv_bfloat162*>(Lp + off) = L;
}

// ===========================================================================
// k_cvt: float4-vectorized hi/lo conversion of X and W1/W2/W3a.
// X: 524288 float4 | W: 3*16384 float4. grid 2240 x 256 (exact).
// ===========================================================================
__global__ void k_cvt(const float4* __restrict__ X4, const float4* __restrict__ W14,
                      const float4* __restrict__ W24, const float4* __restrict__ W34)
{
    const int idx = blockIdx.x * 256 + threadIdx.x;
    if (idx < 524288) {
        const float4 v = X4[idx];
        const size_t o = (size_t)idx * 4;
        split_store(g_Xh, g_Xl, o,     v.x, v.y);
        split_store(g_Xh, g_Xl, o + 2, v.z, v.w);
    } else {
        const int w = idx - 524288;
        const int which = w >> 14;
        const int off4 = w & 16383;
        const float4* S = (which == 0) ? W14 : (which == 1) ? W24 : W34;
        bf16* Hd = (which == 0) ? g_W1h : (which == 1) ? g_W2h : g_W3ah;
        bf16* Ld = (which == 0) ? g_W1l : (which == 1) ? g_W2l : g_W3al;
        const float4 v = S[off4];
        const size_t o = (size_t)off4 * 4;
        split_store(Hd, Ld, o,     v.x, v.y);
        split_store(Hd, Ld, o + 2, v.z, v.w);
    }
}

// ===========================================================================
// Core: multi-pass bf16 MMA GEMM, A row-major [M][256], B row-major [256][N].
// Block tile 128x128, 8 warps (2m x 4n), warp tile 64x32, k-tile 32.
// 3-stage cp.async ring, ONE __syncthreads per k-tile.
// Dynamic smem: As 3*128*40 bf16 (30720B) + Bs 3*32*136 bf16 (26112B) = 56832B
// ===========================================================================
#define AS_ELEM(b, r, c) sAs[(b) * 5120 + (r) * 40 + (c)]
#define BS_ELEM(b, r, c) sBs[(b) * 4352 + (r) * 136 + (c)]

template <int NPASS>
__device__ __forceinline__ void mma_core_rowA(
    const bf16* const* Ap, const bf16* const* Bp,
    int rowBase, int colBase, float (&acc)[4][4][4])
{
    extern __shared__ __align__(16) char sm_raw[];
    bf16* sAs = (bf16*)sm_raw;
    bf16* sBs = (bf16*)(sm_raw + 30720);

    const int tid = threadIdx.x;
    const int lane = tid & 31, w = tid >> 5;
    const int m0w = (w >> 2) * 64, n0w = (w & 3) * 32;

    const int a0r = tid >> 2,  a0o = (tid & 3) * 8;   // A: 128 rows x 32k
    const int a1r = a0r + 64;
    const int b0r = tid >> 4,  b0o = (tid & 15) * 8;  // B: 32k x 128n
    const int b1r = b0r + 16;

    auto prefetch = [&](int it, int bufn) {
        const int pass = it >> 3;
        const int k0 = (it & 7) * 32;
        const bf16* __restrict__ A = Ap[pass];
        const bf16* __restrict__ B = Bp[pass];
        cpa16(&AS_ELEM(bufn, a0r, a0o), A + (size_t)(rowBase + a0r) * DD + k0 + a0o);
        cpa16(&AS_ELEM(bufn, a1r, a0o), A + (size_t)(rowBase + a1r) * DD + k0 + a0o);
        cpa16(&BS_ELEM(bufn, b0r, b0o), B + (size_t)(k0 + b0r) * DD + colBase + b0o);
        cpa16(&BS_ELEM(bufn, b1r, b0o), B + (size_t)(k0 + b1r) * DD + colBase + b0o);
        cpa_commit();
    };

    const int t = lane >> 3;
    const int aro = (t & 1) * 8 + (lane & 7);
    const int aco = (t >> 1) * 8;
    const int bro = lane & 15;

    constexpr int NIT = NPASS * 8;
    prefetch(0, 0);
    prefetch(1, 1);
    for (int it = 0; it < NIT; ++it) {
        cpa_wait1();
        __syncthreads();
        if (it + 2 < NIT) prefetch(it + 2, (it + 2) % 3);
        const int buf = it % 3;
#pragma unroll
        for (int ki = 0; ki < 2; ++ki) {
            u32 a[4][4], b[4][2];
#pragma unroll
            for (int mi = 0; mi < 4; ++mi)
                ldsm_x4(a[mi], saddr(&AS_ELEM(buf, m0w + mi * 16 + aro, ki * 16 + aco)));
#pragma unroll
            for (int ni = 0; ni < 4; ++ni)
                ldsm_x2_t(b[ni], saddr(&BS_ELEM(buf, ki * 16 + bro, n0w + ni * 8)));
#pragma unroll
            for (int mi = 0; mi < 4; ++mi)
#pragma unroll
                for (int ni = 0; ni < 4; ++ni)
                    mma_bf16(acc[mi][ni], a[mi], b[ni]);
        }
    }
}

// ===========================================================================
// k_e_mma: e_z = relu(X @ W_z + b_z) -> bf16 hi/lo. grid (2, 64, 2) x 256.
// ===========================================================================
__global__ void k_e_mma(const float* __restrict__ b1, const float* __restrict__ b2)
{
    const int z = blockIdx.z;
    const bf16* Ap[3] = {g_Xh, g_Xh, g_Xl};
    const bf16* Bp[3] = {z ? g_W2h : g_W1h, z ? g_W2l : g_W1l, z ? g_W2h : g_W1h};
    const float* __restrict__ bias = z ? b2 : b1;
    bf16* __restrict__ Eh = g_eh[z];
    bf16* __restrict__ El = g_el[z];

    const int rowBase = blockIdx.y * 128, colBase = blockIdx.x * 128;
    float acc[4][4][4] = {};
    mma_core_rowA<3>(Ap, Bp, rowBase, colBase, acc);

    const int lane = threadIdx.x & 31, w = threadIdx.x >> 5;
    const int m0w = (w >> 2) * 64, n0w = (w & 3) * 32;
    const int r_l = lane >> 2, c_l = (lane & 3) * 2;
#pragma unroll
    for (int mi = 0; mi < 4; ++mi)
#pragma unroll
        for (int ni = 0; ni < 4; ++ni) {
            const int col = colBase + n0w + ni * 8 + c_l;
            const float2 bb = *(const float2*)&bias[col];
#pragma unroll
            for (int h = 0; h < 2; ++h) {
                const int r = rowBase + m0w + mi * 16 + r_l + h * 8;
                float v0 = fmaxf(acc[mi][ni][h * 2 + 0] + bb.x, 0.f);
                float v1 = fmaxf(acc[mi][ni][h * 2 + 1] + bb.y, 0.f);
                split_store(Eh, El, (size_t)r * DD + col, v0, v1);
            }
        }
}

// ===========================================================================
// k_mpart_mma: split-K partials of M_z = e_zᵀ @ X (trans-A ldmatrix).
// grid (2, 2, 32) x 256, 3-stage ring.
// Dynamic smem: Es 3*32*136 + Xs 3*32*136 bf16 = 52224B.
// ===========================================================================
#define ES_ELEM(b, r, c) sEs[(b) * 4352 + (r) * 136 + (c)]
#define XS_ELEM(b, r, c) sXs[(b) * 4352 + (r) * 136 + (c)]

__global__ void k_mpart_mma()
{
    const int mat = blockIdx.z >> 4, split = blockIdx.z & 15;
    const bf16* Ap[3] = {g_eh[mat], g_eh[mat], g_el[mat]};
    const bf16* Bp[3] = {g_Xh, g_Xl, g_Xh};
    float* __restrict__ Cp = g_Mpart[mat][split];

    extern __shared__ __align__(16) char sm_raw[];
    bf16* sEs = (bf16*)sm_raw;
    bf16* sXs = (bf16*)(sm_raw + 26112);

    const int tid = threadIdx.x;
    const int lane = tid & 31, w = tid >> 5;
    const int m0w = (w >> 2) * 64, n0w = (w & 3) * 32;
    const int mBase = blockIdx.y * 128, nBase = blockIdx.x * 128;
    const int i0 = split * (NEDGE / SPLITK);

    const int c0r = tid >> 4, c0o = (tid & 15) * 8;
    const int c1r = c0r + 16;

    auto prefetch = [&](int it, int bufn) {
        const int pass = it >> 4;
        const int e0 = i0 + (it & 15) * 32;
        const bf16* __restrict__ E = Ap[pass];
        const bf16* __restrict__ X = Bp[pass];
        cpa16(&ES_ELEM(bufn, c0r, c0o), E + (size_t)(e0 + c0r) * DD + mBase + c0o);
        cpa16(&ES_ELEM(bufn, c1r, c0o), E + (size_t)(e0 + c1r) * DD + mBase + c0o);
        cpa16(&XS_ELEM(bufn, c0r, c0o), X + (size_t)(e0 + c0r) * DD + nBase + c0o);
        cpa16(&XS_ELEM(bufn, c1r, c0o), X + (size_t)(e0 + c1r) * DD + nBase + c0o);
        cpa_commit();
    };

    const int t = lane >> 3;
    const int akro = (t >> 1) * 8 + (lane & 7);
    const int amco = (t & 1) * 8;
    const int bro = lane & 15;

    float acc[4][4][4] = {};
    prefetch(0, 0);
    prefetch(1, 1);
    for (int it = 0; it < 48; ++it) {
        cpa_wait1();
        __syncthreads();
        if (it + 2 < 48) prefetch(it + 2, (it + 2) % 3);
        const int buf = it % 3;
#pragma unroll
        for (int ki = 0; ki < 2; ++ki) {
            u32 a[4][4], b[4][2];
#pragma unroll
            for (int mi = 0; mi < 4; ++mi)
                ldsm_x4_t(a[mi], saddr(&ES_ELEM(buf, ki * 16 + akro, m0w + mi * 16 + amco)));
#pragma unroll
            for (int ni = 0; ni < 4; ++ni)
                ldsm_x2_t(b[ni], saddr(&XS_ELEM(buf, ki * 16 + bro, n0w + ni * 8)));
#pragma unroll
            for (int mi = 0; mi < 4; ++mi)
#pragma unroll
                for (int ni = 0; ni < 4; ++ni)
                    mma_bf16(acc[mi][ni], a[mi], b[ni]);
        }
    }

    const int r_l = lane >> 2, c_l = (lane & 3) * 2;
#pragma unroll
    for (int mi = 0; mi < 4; ++mi)
#pragma unroll
        for (int ni = 0; ni < 4; ++ni) {
            const int col = nBase + n0w + ni * 8 + c_l;
#pragma unroll
            for (int h = 0; h < 2; ++h) {
                const int r = mBase + m0w + mi * 16 + r_l + h * 8;
                float2 v = make_float2(acc[mi][ni][h * 2 + 0], acc[mi][ni][h * 2 + 1]);
                *(float2*)&Cp[(size_t)r * DD + col] = v;
            }
        }
}

// ===========================================================================
// k_mreduce: float4 reduce of M partials, scale 1/D. grid 128 x 256.
// ===========================================================================
__global__ void k_mreduce()
{
    const int idx = blockIdx.x * 256 + threadIdx.x;   // 0..32767
    const int mat = idx >> 14;
    const int o4 = (idx & 16383) * 4;
    float4 s = *(const float4*)&g_Mpart[mat][0][o4];
#pragma unroll
    for (int p = 1; p < SPLITK; p++) {
        const float4 v = *(const float4*)&g_Mpart[mat][p][o4];
        s.x += v.x; s.y += v.y; s.z += v.z; s.w += v.w;
    }
    const float sc = 1.0f / DD;
    s.x *= sc; s.y *= sc; s.z *= sc; s.w *= sc;
    *(float4*)&g_M[mat][o4] = s;
}

// ===========================================================================
// k_p: P partials = M_z @ W3b_z, split-K x4 (fp32). grid (8, 8, 8) x 256.
// ===========================================================================
__global__ void k_p(const float* __restrict__ W3)
{
    const int mat = blockIdx.z >> 2, ks = blockIdx.z & 3;
    const float* __restrict__ A = g_M[mat];
    const float* __restrict__ B = W3 + (size_t)(DD + mat * DD) * DD;
    float* __restrict__ Cp = g_Ppart[mat][ks];

    __shared__ __align__(16) float As[32][68];
    __shared__ __align__(16) float Bs[64][36];

    const int tid = threadIdx.x;
    const int mBase = blockIdx.y * 32, nBase = blockIdx.x * 32, k0 = ks * 64;

    {
        const int c0 = tid, c1 = tid + 256;
        cpa16(&As[c0 >> 4][(c0 & 15) * 4], &A[(size_t)(mBase + (c0 >> 4)) * DD + k0 + (c0 & 15) * 4]);
        cpa16(&As[c1 >> 4][(c1 & 15) * 4], &A[(size_t)(mBase + (c1 >> 4)) * DD + k0 + (c1 & 15) * 4]);
        cpa16(&Bs[c0 >> 3][(c0 & 7) * 4], &B[(size_t)(k0 + (c0 >> 3)) * DD + nBase + (c0 & 7) * 4]);
        cpa16(&Bs[c1 >> 3][(c1 & 7) * 4], &B[(size_t)(k0 + (c1 >> 3)) * DD + nBase + (c1 & 7) * 4]);
        cpa_commit(); cpa_wait0();
        __syncthreads();
    }

    const int ty = tid >> 4, tx = tid & 15;
    float a00 = 0.f, a01 = 0.f, a10 = 0.f, a11 = 0.f;
#pragma unroll
    for (int kk = 0; kk < 64; kk++) {
        const float av0 = As[ty * 2 + 0][kk];
        const float av1 = As[ty * 2 + 1][kk];
        const float2 bv = *(const float2*)&Bs[kk][tx * 2];
        a00 = fmaf(av0, bv.x, a00); a01 = fmaf(av0, bv.y, a01);
        a10 = fmaf(av1, bv.x, a10); a11 = fmaf(av1, bv.y, a11);
    }
    *(float2*)&Cp[(size_t)(mBase + ty * 2 + 0) * DD + nBase + tx * 2] = make_float2(a00, a01);
    *(float2*)&Cp[(size_t)(mBase + ty * 2 + 1) * DD + nBase + tx * 2] = make_float2(a10, a11);
}

// ===========================================================================
// k_pcvt: float4 reduce P partials + convert to bf16 hi/lo. grid 128 x 256.
// ===========================================================================
__global__ void k_pcvt()
{
    const int idx = blockIdx.x * 256 + threadIdx.x;   // 0..32767
    const int mat = idx >> 14;
    const int o4 = (idx & 16383) * 4;
    float4 s = *(const float4*)&g_Ppart[mat][0][o4];
#pragma unroll
    for (int p = 1; p < 4; p++) {
        const float4 v = *(const float4*)&g_Ppart[mat][p][o4];
        s.x += v.x; s.y += v.y; s.z += v.z; s.w += v.w;
    }
    split_store(g_Ph[mat], g_Pl[mat], o4,     s.x, s.y);
    split_store(g_Ph[mat], g_Pl[mat], o4 + 2, s.z, s.w);
}

// ===========================================================================
// k_final_mma: out = relu(X@W3a + e1@P1 + e2@P2 + b3). 9 passes. grid (2,64).
// ===========================================================================
__global__ void k_final_mma(const float* __restrict__ b3, float* __restrict__ out)
{
    const bf16* Ap[9] = {g_Xh, g_Xh, g_Xl,
                         g_eh[0], g_eh[0], g_el[0],
                         g_eh[1], g_eh[1], g_el[1]};
    const bf16* Bp[9] = {g_W3ah, g_W3al, g_W3ah,
                         g_Ph[0], g_Pl[0], g_Ph[0],
                         g_Ph[1], g_Pl[1], g_Ph[1]};

    const int rowBase = blockIdx.y * 128, colBase = blockIdx.x * 128;
    float acc[4][4][4] = {};
    mma_core_rowA<9>(Ap, Bp, rowBase, colBase, acc);

    const int lane = threadIdx.x & 31, w = threadIdx.x >> 5;
    const int m0w = (w >> 2) * 64, n0w = (w & 3) * 32;
    const int r_l = lane >> 2, c_l = (lane & 3) * 2;
#pragma unroll
    for (int mi = 0; mi < 4; ++mi)
#pragma unroll
        for (int ni = 0; ni < 4; ++ni) {
            const int col = colBase + n0w + ni * 8 + c_l;
            const float2 bb = *(const float2*)&b3[col];
#pragma unroll
            for (int h = 0; h < 2; ++h) {
                const int r = rowBase + m0w + mi * 16 + r_l + h * 8;
                float2 v;
                v.x = fmaxf(acc[mi][ni][h * 2 + 0] + bb.x, 0.f);
                v.y = fmaxf(acc[mi][ni][h * 2 + 1] + bb.y, 0.f);
                *(float2*)&out[(size_t)r * DD + col] = v;
            }
        }
}

// ---------------------------------------------------------------------------
// Inputs (metadata order):
// 0 edge_pred[8192] f32 | 1 edge_corner[8192,2] i64 | 2 all_corners[4096,2] f32
// 3 edge_x[8192,256] f32 | 4 image_x[1024] f32 | 5 W1[256,256] | 6 b1[256]
// 7 W2[256,256] | 8 b2[256] | 9 W3[768,256] | 10 b3[256]
// Output: [8192, 256] f32
// ---------------------------------------------------------------------------
extern "C" void kernel_launch(void* const* d_in, const int* in_sizes, int n_in,
                              void* d_out, int out_size)
{
    (void)in_sizes; (void)n_in; (void)out_size;
    const float* X  = (const float*)d_in[3];
    const float* W1 = (const float*)d_in[5];
    const float* b1 = (const float*)d_in[6];
    const float* W2 = (const float*)d_in[7];
    const float* b2 = (const float*)d_in[8];
    const float* W3 = (const float*)d_in[9];
    const float* b3 = (const float*)d_in[10];
    float* out = (float*)d_out;

    const int SMEM_CORE  = 30720 + 26112;  // 56832 B
    const int SMEM_MPART = 2 * 26112;      // 52224 B
    static bool attr_done = false;
    cudaFuncSetAttribute(k_e_mma, cudaFuncAttributeMaxDynamicSharedMemorySize, SMEM_CORE);
    cudaFuncSetAttribute(k_final_mma, cudaFuncAttributeMaxDynamicSharedMemorySize, SMEM_CORE);
    cudaFuncSetAttribute(k_mpart_mma, cudaFuncAttributeMaxDynamicSharedMemorySize, SMEM_MPART);
    (void)attr_done;

    k_cvt<<<2240, 256>>>((const float4*)X, (const float4*)W1,
                         (const float4*)W2, (const float4*)W3);
    k_e_mma<<<dim3(2, 64, 2), 256, SMEM_CORE>>>(b1, b2);
    k_mpart_mma<<<dim3(2, 2, 32), 256, SMEM_MPART>>>();
    k_mreduce<<<128, 256>>>();
    k_p<<<dim3(8, 8, 8), 256>>>(W3);
    k_pcvt<<<128, 256>>>();
    k_final_mma<<<dim3(2, 64), 256, SMEM_CORE>>>(b3, out);
}

// round 7
// speedup vs baseline: 2.3503x; 1.0733x over previous
#include <cuda_runtime.h>
#include <cuda_bf16.h>

#define NEDGE 8192
#define DD    256
#define SPLITK 16

typedef __nv_bfloat16 bf16;
typedef unsigned int u32;

// ---------------- scratch (device globals; no allocation allowed) ----------
__device__ __align__(16) bf16 g_Xh[NEDGE * DD], g_Xl[NEDGE * DD];
__device__ __align__(16) bf16 g_eh[2][NEDGE * DD], g_el[2][NEDGE * DD];
__device__ __align__(16) bf16 g_W1h[DD * DD], g_W1l[DD * DD];
__device__ __align__(16) bf16 g_W2h[DD * DD], g_W2l[DD * DD];
__device__ __align__(16) bf16 g_W3ah[DD * DD], g_W3al[DD * DD];
__device__ __align__(16) bf16 g_Ph[2][DD * DD], g_Pl[2][DD * DD];
__device__ float g_Mpart[2][SPLITK][DD * DD];
__device__ float g_M[2][DD * DD];
__device__ float g_Ppart[2][4][DD * DD];

// ---------------- helpers ---------------------------------------------------
__device__ __forceinline__ void cpa16(void* dst, const void* src) {
    unsigned s = (unsigned)__cvta_generic_to_shared(dst);
    asm volatile("cp.async.cg.shared.global [%0], [%1], 16;" :: "r"(s), "l"(src));
}
__device__ __forceinline__ void cpa_commit() { asm volatile("cp.async.commit_group;"); }
__device__ __forceinline__ void cpa_wait0()  { asm volatile("cp.async.wait_group 0;"); }
__device__ __forceinline__ void cpa_wait1()  { asm volatile("cp.async.wait_group 1;"); }

__device__ __forceinline__ unsigned saddr(const void* p) {
    return (unsigned)__cvta_generic_to_shared(p);
}
__device__ __forceinline__ void ldsm_x4(u32* r, unsigned a) {
    asm volatile("ldmatrix.sync.aligned.m8n8.x4.shared.b16 {%0,%1,%2,%3}, [%4];"
        : "=r"(r[0]), "=r"(r[1]), "=r"(r[2]), "=r"(r[3]) : "r"(a));
}
__device__ __forceinline__ void ldsm_x4_t(u32* r, unsigned a) {
    asm volatile("ldmatrix.sync.aligned.m8n8.x4.trans.shared.b16 {%0,%1,%2,%3}, [%4];"
        : "=r"(r[0]), "=r"(r[1]), "=r"(r[2]), "=r"(r[3]) : "r"(a));
}
__device__ __forceinline__ void mma_bf16(float* d, const u32* a, const u32* b) {
    asm volatile(
        "mma.sync.aligned.m16n8k16.row.col.f32.bf16.bf16.f32 "
        "{%0,%1,%2,%3}, {%4,%5,%6,%7}, {%8,%9}, {%0,%1,%2,%3};"
        : "+f"(d[0]), "+f"(d[1]), "+f"(d[2]), "+f"(d[3])
        : "r"(a[0]), "r"(a[1]), "r"(a[2]), "r"(a[3]), "r"(b[0]), "r"(b[1]));
}
__device__ __forceinline__ void split_store(bf16* Hp, bf16* Lp, size_t off,
                                            float v0, float v1) {
    bf16 h0 = __float2bfloat16(v0), h1 = __float2bfloat16(v1);
    bf16 l0 = __float2bfloat16(v0 - __bfloat162float(h0));
    bf16 l1 = __float2bfloat16(v1 - __bfloat162float(h1));
    __nv_bfloat162 H; H.x = h0; H.y = h1;
    __nv_bfloat162 L; L.x = l0; L.y = l1;
    *reinterpret_cast<__nv_bfloat162*>(Hp + off) = H;
    *reinterpret_cast<__nv_bfloat162*>(Lp + off) = L;
}

// ===========================================================================
// k_cvt: float4-vectorized hi/lo conversion of X and W1/W2/W3a.
// grid 2240 x 256 (exact).
// ===========================================================================
__global__ void k_cvt(const float4* __restrict__ X4, const float4* __restrict__ W14,
                      const float4* __restrict__ W24, const float4* __restrict__ W34)
{
    const int idx = blockIdx.x * 256 + threadIdx.x;
    if (idx < 524288) {
        const float4 v = X4[idx];
        const size_t o = (size_t)idx * 4;
        split_store(g_Xh, g_Xl, o,     v.x, v.y);
        split_store(g_Xh, g_Xl, o + 2, v.z, v.w);
    } else {
        const int w = idx - 524288;
        const int which = w >> 14;
        const int off4 = w & 16383;
        const float4* S = (which == 0) ? W14 : (which == 1) ? W24 : W34;
        bf16* Hd = (which == 0) ? g_W1h : (which == 1) ? g_W2h : g_W3ah;
        bf16* Ld = (which == 0) ? g_W1l : (which == 1) ? g_W2l : g_W3al;
        const float4 v = S[off4];
        const size_t o = (size_t)off4 * 4;
        split_store(Hd, Ld, o,     v.x, v.y);
        split_store(Hd, Ld, o + 2, v.z, v.w);
    }
}

// ===========================================================================
// Core: multi-pass bf16 MMA GEMM. Block tile 128x128, 8 warps (2m x 4n),
// warp tile 64x32, k-tile 32, 3-stage cp.async ring.
// B fetched with ldmatrix.x4.trans (16x16 per issue).
// ===========================================================================
#define AS_ELEM(b, r, c) sAs[(b) * 5120 + (r) * 40 + (c)]
#define BS_ELEM(b, r, c) sBs[(b) * 4352 + (r) * 136 + (c)]

template <int NPASS>
__device__ __forceinline__ void mma_core_rowA(
    const bf16* const* Ap, const bf16* const* Bp,
    int rowBase, int colBase, float (&acc)[4][4][4])
{
    extern __shared__ __align__(16) char sm_raw[];
    bf16* sAs = (bf16*)sm_raw;
    bf16* sBs = (bf16*)(sm_raw + 30720);

    const int tid = threadIdx.x;
    const int lane = tid & 31, w = tid >> 5;
    const int m0w = (w >> 2) * 64, n0w = (w & 3) * 32;

    const int a0r = tid >> 2,  a0o = (tid & 3) * 8;
    const int a1r = a0r + 64;
    const int b0r = tid >> 4,  b0o = (tid & 15) * 8;
    const int b1r = b0r + 16;

    auto prefetch = [&](int it, int bufn) {
        const int pass = it >> 3;
        const int k0 = (it & 7) * 32;
        const bf16* __restrict__ A = Ap[pass];
        const bf16* __restrict__ B = Bp[pass];
        cpa16(&AS_ELEM(bufn, a0r, a0o), A + (size_t)(rowBase + a0r) * DD + k0 + a0o);
        cpa16(&AS_ELEM(bufn, a1r, a0o), A + (size_t)(rowBase + a1r) * DD + k0 + a0o);
        cpa16(&BS_ELEM(bufn, b0r, b0o), B + (size_t)(k0 + b0r) * DD + colBase + b0o);
        cpa16(&BS_ELEM(bufn, b1r, b0o), B + (size_t)(k0 + b1r) * DD + colBase + b0o);
        cpa_commit();
    };

    const int t = lane >> 3;
    const int aro = (t & 1) * 8 + (lane & 7);
    const int aco = (t >> 1) * 8;
    // B x4.trans addressing: 4 blocks = (k0-7,nA),(k8-15,nA),(k0-7,nB),(k8-15,nB)
    const int bro2 = (lane & 7) + ((lane >> 3) & 1) * 8;
    const int bco2 = (lane >> 4) * 8;

    constexpr int NIT = NPASS * 8;
    prefetch(0, 0);
    prefetch(1, 1);
    for (int it = 0; it < NIT; ++it) {
        cpa_wait1();
        __syncthreads();
        if (it + 2 < NIT) prefetch(it + 2, (it + 2) % 3);
        const int buf = it % 3;
#pragma unroll
        for (int ki = 0; ki < 2; ++ki) {
            u32 a[4][4], bq[2][4];
#pragma unroll
            for (int mi = 0; mi < 4; ++mi)
                ldsm_x4(a[mi], saddr(&AS_ELEM(buf, m0w + mi * 16 + aro, ki * 16 + aco)));
#pragma unroll
            for (int nj = 0; nj < 2; ++nj)
                ldsm_x4_t(bq[nj], saddr(&BS_ELEM(buf, ki * 16 + bro2, n0w + nj * 16 + bco2)));
#pragma unroll
            for (int mi = 0; mi < 4; ++mi)
#pragma unroll
                for (int ni = 0; ni < 4; ++ni)
                    mma_bf16(acc[mi][ni], a[mi], &bq[ni >> 1][(ni & 1) * 2]);
        }
    }
}

// ===========================================================================
// k_e_mma: e_z = relu(X @ W_z + b_z) -> bf16 hi/lo. grid (2, 64, 2) x 256.
// ===========================================================================
__global__ void __launch_bounds__(256, 2)
k_e_mma(const float* __restrict__ b1, const float* __restrict__ b2)
{
    const int z = blockIdx.z;
    const bf16* Ap[3] = {g_Xh, g_Xh, g_Xl};
    const bf16* Bp[3] = {z ? g_W2h : g_W1h, z ? g_W2l : g_W1l, z ? g_W2h : g_W1h};
    const float* __restrict__ bias = z ? b2 : b1;
    bf16* __restrict__ Eh = g_eh[z];
    bf16* __restrict__ El = g_el[z];

    const int rowBase = blockIdx.y * 128, colBase = blockIdx.x * 128;
    float acc[4][4][4] = {};
    mma_core_rowA<3>(Ap, Bp, rowBase, colBase, acc);

    const int lane = threadIdx.x & 31, w = threadIdx.x >> 5;
    const int m0w = (w >> 2) * 64, n0w = (w & 3) * 32;
    const int r_l = lane >> 2, c_l = (lane & 3) * 2;
#pragma unroll
    for (int mi = 0; mi < 4; ++mi)
#pragma unroll
        for (int ni = 0; ni < 4; ++ni) {
            const int col = colBase + n0w + ni * 8 + c_l;
            const float2 bb = *(const float2*)&bias[col];
#pragma unroll
            for (int h = 0; h < 2; ++h) {
                const int r = rowBase + m0w + mi * 16 + r_l + h * 8;
                float v0 = fmaxf(acc[mi][ni][h * 2 + 0] + bb.x, 0.f);
                float v1 = fmaxf(acc[mi][ni][h * 2 + 1] + bb.y, 0.f);
                split_store(Eh, El, (size_t)r * DD + col, v0, v1);
            }
        }
}

// ===========================================================================
// k_mpart_mma: split-K partials of M_z = e_zᵀ @ X (trans-A ldmatrix).
// grid (2, 2, 32) x 256, 3-stage ring.
// ===========================================================================
#define ES_ELEM(b, r, c) sEs[(b) * 4352 + (r) * 136 + (c)]
#define XS_ELEM(b, r, c) sXs[(b) * 4352 + (r) * 136 + (c)]

__global__ void __launch_bounds__(256, 2)
k_mpart_mma()
{
    const int mat = blockIdx.z >> 4, split = blockIdx.z & 15;
    const bf16* Ap[3] = {g_eh[mat], g_eh[mat], g_el[mat]};
    const bf16* Bp[3] = {g_Xh, g_Xl, g_Xh};
    float* __restrict__ Cp = g_Mpart[mat][split];

    extern __shared__ __align__(16) char sm_raw[];
    bf16* sEs = (bf16*)sm_raw;
    bf16* sXs = (bf16*)(sm_raw + 26112);

    const int tid = threadIdx.x;
    const int lane = tid & 31, w = tid >> 5;
    const int m0w = (w >> 2) * 64, n0w = (w & 3) * 32;
    const int mBase = blockIdx.y * 128, nBase = blockIdx.x * 128;
    const int i0 = split * (NEDGE / SPLITK);

    const int c0r = tid >> 4, c0o = (tid & 15) * 8;
    const int c1r = c0r + 16;

    auto prefetch = [&](int it, int bufn) {
        const int pass = it >> 4;
        const int e0 = i0 + (it & 15) * 32;
        const bf16* __restrict__ E = Ap[pass];
        const bf16* __restrict__ X = Bp[pass];
        cpa16(&ES_ELEM(bufn, c0r, c0o), E + (size_t)(e0 + c0r) * DD + mBase + c0o);
        cpa16(&ES_ELEM(bufn, c1r, c0o), E + (size_t)(e0 + c1r) * DD + mBase + c0o);
        cpa16(&XS_ELEM(bufn, c0r, c0o), X + (size_t)(e0 + c0r) * DD + nBase + c0o);
        cpa16(&XS_ELEM(bufn, c1r, c0o), X + (size_t)(e0 + c1r) * DD + nBase + c0o);
        cpa_commit();
    };

    const int t = lane >> 3;
    const int akro = (t >> 1) * 8 + (lane & 7);
    const int amco = (t & 1) * 8;
    const int bro2 = (lane & 7) + ((lane >> 3) & 1) * 8;
    const int bco2 = (lane >> 4) * 8;

    float acc[4][4][4] = {};
    prefetch(0, 0);
    prefetch(1, 1);
    for (int it = 0; it < 48; ++it) {
        cpa_wait1();
        __syncthreads();
        if (it + 2 < 48) prefetch(it + 2, (it + 2) % 3);
        const int buf = it % 3;
#pragma unroll
        for (int ki = 0; ki < 2; ++ki) {
            u32 a[4][4], bq[2][4];
#pragma unroll
            for (int mi = 0; mi < 4; ++mi)
                ldsm_x4_t(a[mi], saddr(&ES_ELEM(buf, ki * 16 + akro, m0w + mi * 16 + amco)));
#pragma unroll
            for (int nj = 0; nj < 2; ++nj)
                ldsm_x4_t(bq[nj], saddr(&XS_ELEM(buf, ki * 16 + bro2, n0w + nj * 16 + bco2)));
#pragma unroll
            for (int mi = 0; mi < 4; ++mi)
#pragma unroll
                for (int ni = 0; ni < 4; ++ni)
                    mma_bf16(acc[mi][ni], a[mi], &bq[ni >> 1][(ni & 1) * 2]);
        }
    }

    const int r_l = lane >> 2, c_l = (lane & 3) * 2;
#pragma unroll
    for (int mi = 0; mi < 4; ++mi)
#pragma unroll
        for (int ni = 0; ni < 4; ++ni) {
            const int col = nBase + n0w + ni * 8 + c_l;
#pragma unroll
            for (int h = 0; h < 2; ++h) {
                const int r = mBase + m0w + mi * 16 + r_l + h * 8;
                float2 v = make_float2(acc[mi][ni][h * 2 + 0], acc[mi][ni][h * 2 + 1]);
                *(float2*)&Cp[(size_t)r * DD + col] = v;
            }
        }
}

// ===========================================================================
// k_mreduce: 4-way thread-split + deterministic shfl_xor tree. grid 512 x 256.
// Thread group of 4 shares one float4 output; thread q sums partials 4q..4q+3.
// ===========================================================================
__global__ void k_mreduce()
{
    const int gid = blockIdx.x * 256 + threadIdx.x;   // 0..131071
    const int q4 = (gid & 3) * 4;
    const int o = gid >> 2;                           // 0..32767
    const int mat = o >> 14;
    const int o4 = (o & 16383) * 4;
    float4 s = *(const float4*)&g_Mpart[mat][q4][o4];
#pragma unroll
    for (int p = 1; p < 4; p++) {
        const float4 v = *(const float4*)&g_Mpart[mat][q4 + p][o4];
        s.x += v.x; s.y += v.y; s.z += v.z; s.w += v.w;
    }
#pragma unroll
    for (int d = 1; d <= 2; d <<= 1) {
        s.x += __shfl_xor_sync(0xffffffffu, s.x, d);
        s.y += __shfl_xor_sync(0xffffffffu, s.y, d);
        s.z += __shfl_xor_sync(0xffffffffu, s.z, d);
        s.w += __shfl_xor_sync(0xffffffffu, s.w, d);
    }
    if ((gid & 3) == 0) {
        const float sc = 1.0f / DD;
        s.x *= sc; s.y *= sc; s.z *= sc; s.w *= sc;
        *(float4*)&g_M[mat][o4] = s;
    }
}

// ===========================================================================
// k_p: P partials = M_z @ W3b_z, split-K x4 (fp32). grid (8, 8, 8) x 256.
// ===========================================================================
__global__ void k_p(const float* __restrict__ W3)
{
    const int mat = blockIdx.z >> 2, ks = blockIdx.z & 3;
    const float* __restrict__ A = g_M[mat];
    const float* __restrict__ B = W3 + (size_t)(DD + mat * DD) * DD;
    float* __restrict__ Cp = g_Ppart[mat][ks];

    __shared__ __align__(16) float As[32][68];
    __shared__ __align__(16) float Bs[64][36];

    const int tid = threadIdx.x;
    const int mBase = blockIdx.y * 32, nBase = blockIdx.x * 32, k0 = ks * 64;

    {
        const int c0 = tid, c1 = tid + 256;
        cpa16(&As[c0 >> 4][(c0 & 15) * 4], &A[(size_t)(mBase + (c0 >> 4)) * DD + k0 + (c0 & 15) * 4]);
        cpa16(&As[c1 >> 4][(c1 & 15) * 4], &A[(size_t)(mBase + (c1 >> 4)) * DD + k0 + (c1 & 15) * 4]);
        cpa16(&Bs[c0 >> 3][(c0 & 7) * 4], &B[(size_t)(k0 + (c0 >> 3)) * DD + nBase + (c0 & 7) * 4]);
        cpa16(&Bs[c1 >> 3][(c1 & 7) * 4], &B[(size_t)(k0 + (c1 >> 3)) * DD + nBase + (c1 & 7) * 4]);
        cpa_commit(); cpa_wait0();
        __syncthreads();
    }

    const int ty = tid >> 4, tx = tid & 15;
    float a00 = 0.f, a01 = 0.f, a10 = 0.f, a11 = 0.f;
#pragma unroll
    for (int kk = 0; kk < 64; kk++) {
        const float av0 = As[ty * 2 + 0][kk];
        const float av1 = As[ty * 2 + 1][kk];
        const float2 bv = *(const float2*)&Bs[kk][tx * 2];
        a00 = fmaf(av0, bv.x, a00); a01 = fmaf(av0, bv.y, a01);
        a10 = fmaf(av1, bv.x, a10); a11 = fmaf(av1, bv.y, a11);
    }
    *(float2*)&Cp[(size_t)(mBase + ty * 2 + 0) * DD + nBase + tx * 2] = make_float2(a00, a01);
    *(float2*)&Cp[(size_t)(mBase + ty * 2 + 1) * DD + nBase + tx * 2] = make_float2(a10, a11);
}

// ===========================================================================
// k_pcvt: 2-way thread-split reduce + hi/lo convert. grid 256 x 256.
// ===========================================================================
__global__ void k_pcvt()
{
    const int gid = blockIdx.x * 256 + threadIdx.x;   // 0..65535
    const int q2 = (gid & 1) * 2;
    const int o = gid >> 1;                            // 0..32767
    const int mat = o >> 14;
    const int o4 = (o & 16383) * 4;
    float4 s = *(const float4*)&g_Ppart[mat][q2][o4];
    {
        const float4 v = *(const float4*)&g_Ppart[mat][q2 + 1][o4];
        s.x += v.x; s.y += v.y; s.z += v.z; s.w += v.w;
    }
    s.x += __shfl_xor_sync(0xffffffffu, s.x, 1);
    s.y += __shfl_xor_sync(0xffffffffu, s.y, 1);
    s.z += __shfl_xor_sync(0xffffffffu, s.z, 1);
    s.w += __shfl_xor_sync(0xffffffffu, s.w, 1);
    if ((gid & 1) == 0) {
        split_store(g_Ph[mat], g_Pl[mat], o4,     s.x, s.y);
        split_store(g_Ph[mat], g_Pl[mat], o4 + 2, s.z, s.w);
    }
}

// ===========================================================================
// k_final_mma: out = relu(X@W3a + e1@P1 + e2@P2 + b3). 9 passes. grid (2,64).
// ===========================================================================
__global__ void __launch_bounds__(256, 2)
k_final_mma(const float* __restrict__ b3, float* __restrict__ out)
{
    const bf16* Ap[9] = {g_Xh, g_Xh, g_Xl,
                         g_eh[0], g_eh[0], g_el[0],
                         g_eh[1], g_eh[1], g_el[1]};
    const bf16* Bp[9] = {g_W3ah, g_W3al, g_W3ah,
                         g_Ph[0], g_Pl[0], g_Ph[0],
                         g_Ph[1], g_Pl[1], g_Ph[1]};

    const int rowBase = blockIdx.y * 128, colBase = blockIdx.x * 128;
    float acc[4][4][4] = {};
    mma_core_rowA<9>(Ap, Bp, rowBase, colBase, acc);

    const int lane = threadIdx.x & 31, w = threadIdx.x >> 5;
    const int m0w = (w >> 2) * 64, n0w = (w & 3) * 32;
    const int r_l = lane >> 2, c_l = (lane & 3) * 2;
#pragma unroll
    for (int mi = 0; mi < 4; ++mi)
#pragma unroll
        for (int ni = 0; ni < 4; ++ni) {
            const int col = colBase + n0w + ni * 8 + c_l;
            const float2 bb = *(const float2*)&b3[col];
#pragma unroll
            for (int h = 0; h < 2; ++h) {
                const int r = rowBase + m0w + mi * 16 + r_l + h * 8;
                float2 v;
                v.x = fmaxf(acc[mi][ni][h * 2 + 0] + bb.x, 0.f);
                v.y = fmaxf(acc[mi][ni][h * 2 + 1] + bb.y, 0.f);
                *(float2*)&out[(size_t)r * DD + col] = v;
            }
        }
}

// ---------------------------------------------------------------------------
// Inputs (metadata order):
// 0 edge_pred[8192] f32 | 1 edge_corner[8192,2] i64 | 2 all_corners[4096,2] f32
// 3 edge_x[8192,256] f32 | 4 image_x[1024] f32 | 5 W1[256,256] | 6 b1[256]
// 7 W2[256,256] | 8 b2[256] | 9 W3[768,256] | 10 b3[256]
// Output: [8192, 256] f32
// ---------------------------------------------------------------------------
extern "C" void kernel_launch(void* const* d_in, const int* in_sizes, int n_in,
                              void* d_out, int out_size)
{
    (void)in_sizes; (void)n_in; (void)out_size;
    const float* X  = (const float*)d_in[3];
    const float* W1 = (const float*)d_in[5];
    const float* b1 = (const float*)d_in[6];
    const float* W2 = (const float*)d_in[7];
    const float* b2 = (const float*)d_in[8];
    const float* W3 = (const float*)d_in[9];
    const float* b3 = (const float*)d_in[10];
    float* out = (float*)d_out;

    const int SMEM_CORE  = 30720 + 26112;  // 56832 B
    const int SMEM_MPART = 2 * 26112;      // 52224 B
    cudaFuncSetAttribute(k_e_mma, cudaFuncAttributeMaxDynamicSharedMemorySize, SMEM_CORE);
    cudaFuncSetAttribute(k_final_mma, cudaFuncAttributeMaxDynamicSharedMemorySize, SMEM_CORE);
    cudaFuncSetAttribute(k_mpart_mma, cudaFuncAttributeMaxDynamicSharedMemorySize, SMEM_MPART);

    k_cvt<<<2240, 256>>>((const float4*)X, (const float4*)W1,
                         (const float4*)W2, (const float4*)W3);
    k_e_mma<<<dim3(2, 64, 2), 256, SMEM_CORE>>>(b1, b2);
    k_mpart_mma<<<dim3(2, 2, 32), 256, SMEM_MPART>>>();
    k_mreduce<<<512, 256>>>();
    k_p<<<dim3(8, 8, 8), 256>>>(W3);
    k_pcvt<<<256, 256>>>();
    k_final_mma<<<dim3(2, 64), 256, SMEM_CORE>>>(b3, out);
}

// round 8
// speedup vs baseline: 2.5242x; 1.0740x over previous
#include <cuda_runtime.h>
#include <cuda_bf16.h>

#define NEDGE 8192
#define DD    256
#define SPLITK 16

typedef __nv_bfloat16 bf16;
typedef unsigned int u32;

// ---------------- scratch (device globals; no allocation allowed) ----------
__device__ __align__(16) bf16 g_Xh[NEDGE * DD], g_Xl[NEDGE * DD];
__device__ __align__(16) bf16 g_eh[2][NEDGE * DD], g_el[2][NEDGE * DD];
__device__ __align__(16) bf16 g_W1h[DD * DD], g_W1l[DD * DD];
__device__ __align__(16) bf16 g_W2h[DD * DD], g_W2l[DD * DD];
__device__ __align__(16) bf16 g_W3ah[DD * DD], g_W3al[DD * DD];
__device__ __align__(16) bf16 g_Ph[2][DD * DD], g_Pl[2][DD * DD];
__device__ float g_Mpart[2][SPLITK][DD * DD];
__device__ float g_M[2][DD * DD];
__device__ float g_Ppart[2][4][DD * DD];

// ---------------- helpers ---------------------------------------------------
__device__ __forceinline__ void cpa16(void* dst, const void* src) {
    unsigned s = (unsigned)__cvta_generic_to_shared(dst);
    asm volatile("cp.async.cg.shared.global [%0], [%1], 16;" :: "r"(s), "l"(src));
}
__device__ __forceinline__ void cpa_commit() { asm volatile("cp.async.commit_group;"); }
__device__ __forceinline__ void cpa_wait0()  { asm volatile("cp.async.wait_group 0;"); }
__device__ __forceinline__ void cpa_wait2()  { asm volatile("cp.async.wait_group 2;"); }

__device__ __forceinline__ unsigned saddr(const void* p) {
    return (unsigned)__cvta_generic_to_shared(p);
}
__device__ __forceinline__ void ldsm_x4(u32* r, unsigned a) {
    asm volatile("ldmatrix.sync.aligned.m8n8.x4.shared.b16 {%0,%1,%2,%3}, [%4];"
        : "=r"(r[0]), "=r"(r[1]), "=r"(r[2]), "=r"(r[3]) : "r"(a));
}
__device__ __forceinline__ void ldsm_x4_t(u32* r, unsigned a) {
    asm volatile("ldmatrix.sync.aligned.m8n8.x4.trans.shared.b16 {%0,%1,%2,%3}, [%4];"
        : "=r"(r[0]), "=r"(r[1]), "=r"(r[2]), "=r"(r[3]) : "r"(a));
}
__device__ __forceinline__ void mma_bf16(float* d, const u32* a, const u32* b) {
    asm volatile(
        "mma.sync.aligned.m16n8k16.row.col.f32.bf16.bf16.f32 "
        "{%0,%1,%2,%3}, {%4,%5,%6,%7}, {%8,%9}, {%0,%1,%2,%3};"
        : "+f"(d[0]), "+f"(d[1]), "+f"(d[2]), "+f"(d[3])
        : "r"(a[0]), "r"(a[1]), "r"(a[2]), "r"(a[3]), "r"(b[0]), "r"(b[1]));
}
__device__ __forceinline__ void split_store(bf16* Hp, bf16* Lp, size_t off,
                                            float v0, float v1) {
    bf16 h0 = __float2bfloat16(v0), h1 = __float2bfloat16(v1);
    bf16 l0 = __float2bfloat16(v0 - __bfloat162float(h0));
    bf16 l1 = __float2bfloat16(v1 - __bfloat162float(h1));
    __nv_bfloat162 H; H.x = h0; H.y = h1;
    __nv_bfloat162 L; L.x = l0; L.y = l1;
    *reinterpret_cast<__nv_bfloat162*>(Hp + off) = H;
    *reinterpret_cast<__nv_bfloat162*>(Lp + off) = L;
}

// ===========================================================================
// k_cvt: float4-vectorized hi/lo conversion of X and W1/W2/W3a.
// grid 2240 x 256 (exact).
// ===========================================================================
__global__ void k_cvt(const float4* __restrict__ X4, const float4* __restrict__ W14,
                      const float4* __restrict__ W24, const float4* __restrict__ W34)
{
    const int idx = blockIdx.x * 256 + threadIdx.x;
    if (idx < 524288) {
        const float4 v = X4[idx];
        const size_t o = (size_t)idx * 4;
        split_store(g_Xh, g_Xl, o,     v.x, v.y);
        split_store(g_Xh, g_Xl, o + 2, v.z, v.w);
    } else {
        const int w = idx - 524288;
        const int which = w >> 14;
        const int off4 = w & 16383;
        const float4* S = (which == 0) ? W14 : (which == 1) ? W24 : W34;
        bf16* Hd = (which == 0) ? g_W1h : (which == 1) ? g_W2h : g_W3ah;
        bf16* Ld = (which == 0) ? g_W1l : (which == 1) ? g_W2l : g_W3al;
        const float4 v = S[off4];
        const size_t o = (size_t)off4 * 4;
        split_store(Hd, Ld, o,     v.x, v.y);
        split_store(Hd, Ld, o + 2, v.z, v.w);
    }
}

// ===========================================================================
// Core: multi-pass bf16 MMA GEMM. Block tile 128x128, 8 warps (2m x 4n),
// warp tile 64x32, k-tile 32, 4-stage cp.async ring (3 tiles in flight).
// ===========================================================================
#define AS_ELEM(b, r, c) sAs[(b) * 5120 + (r) * 40 + (c)]
#define BS_ELEM(b, r, c) sBs[(b) * 4352 + (r) * 136 + (c)]

template <int NPASS>
__device__ __forceinline__ void mma_core_rowA(
    const bf16* const* Ap, const bf16* const* Bp,
    int rowBase, int colBase, float (&acc)[4][4][4])
{
    extern __shared__ __align__(16) char sm_raw[];
    bf16* sAs = (bf16*)sm_raw;
    bf16* sBs = (bf16*)(sm_raw + 40960);

    const int tid = threadIdx.x;
    const int lane = tid & 31, w = tid >> 5;
    const int m0w = (w >> 2) * 64, n0w = (w & 3) * 32;

    const int a0r = tid >> 2,  a0o = (tid & 3) * 8;
    const int a1r = a0r + 64;
    const int b0r = tid >> 4,  b0o = (tid & 15) * 8;
    const int b1r = b0r + 16;

    auto prefetch = [&](int it, int bufn) {
        const int pass = it >> 3;
        const int k0 = (it & 7) * 32;
        const bf16* __restrict__ A = Ap[pass];
        const bf16* __restrict__ B = Bp[pass];
        cpa16(&AS_ELEM(bufn, a0r, a0o), A + (size_t)(rowBase + a0r) * DD + k0 + a0o);
        cpa16(&AS_ELEM(bufn, a1r, a0o), A + (size_t)(rowBase + a1r) * DD + k0 + a0o);
        cpa16(&BS_ELEM(bufn, b0r, b0o), B + (size_t)(k0 + b0r) * DD + colBase + b0o);
        cpa16(&BS_ELEM(bufn, b1r, b0o), B + (size_t)(k0 + b1r) * DD + colBase + b0o);
        cpa_commit();
    };

    const int t = lane >> 3;
    const int aro = (t & 1) * 8 + (lane & 7);
    const int aco = (t >> 1) * 8;
    const int bro2 = (lane & 7) + ((lane >> 3) & 1) * 8;
    const int bco2 = (lane >> 4) * 8;

    constexpr int NIT = NPASS * 8;
    prefetch(0, 0);
    prefetch(1, 1);
    prefetch(2, 2);
    for (int it = 0; it < NIT; ++it) {
        cpa_wait2();
        __syncthreads();
        if (it + 3 < NIT) prefetch(it + 3, (it + 3) & 3);
        else cpa_commit();   // empty group keeps wait arithmetic exact
        const int buf = it & 3;
#pragma unroll
        for (int ki = 0; ki < 2; ++ki) {
            u32 a[4][4], bq[2][4];
#pragma unroll
            for (int mi = 0; mi < 4; ++mi)
                ldsm_x4(a[mi], saddr(&AS_ELEM(buf, m0w + mi * 16 + aro, ki * 16 + aco)));
#pragma unroll
            for (int nj = 0; nj < 2; ++nj)
                ldsm_x4_t(bq[nj], saddr(&BS_ELEM(buf, ki * 16 + bro2, n0w + nj * 16 + bco2)));
#pragma unroll
            for (int mi = 0; mi < 4; ++mi)
#pragma unroll
                for (int ni = 0; ni < 4; ++ni)
                    mma_bf16(acc[mi][ni], a[mi], &bq[ni >> 1][(ni & 1) * 2]);
        }
    }
}

// ===========================================================================
// k_e_mma: e_z = relu(X @ W_z + b_z) -> bf16 hi/lo. grid (2, 64, 2) x 256.
// ===========================================================================
__global__ void __launch_bounds__(256, 2)
k_e_mma(const float* __restrict__ b1, const float* __restrict__ b2)
{
    const int z = blockIdx.z;
    const bf16* Ap[3] = {g_Xh, g_Xh, g_Xl};
    const bf16* Bp[3] = {z ? g_W2h : g_W1h, z ? g_W2l : g_W1l, z ? g_W2h : g_W1h};
    const float* __restrict__ bias = z ? b2 : b1;
    bf16* __restrict__ Eh = g_eh[z];
    bf16* __restrict__ El = g_el[z];

    const int rowBase = blockIdx.y * 128, colBase = blockIdx.x * 128;
    float acc[4][4][4] = {};
    mma_core_rowA<3>(Ap, Bp, rowBase, colBase, acc);

    const int lane = threadIdx.x & 31, w = threadIdx.x >> 5;
    const int m0w = (w >> 2) * 64, n0w = (w & 3) * 32;
    const int r_l = lane >> 2, c_l = (lane & 3) * 2;
#pragma unroll
    for (int mi = 0; mi < 4; ++mi)
#pragma unroll
        for (int ni = 0; ni < 4; ++ni) {
            const int col = colBase + n0w + ni * 8 + c_l;
            const float2 bb = *(const float2*)&bias[col];
#pragma unroll
            for (int h = 0; h < 2; ++h) {
                const int r = rowBase + m0w + mi * 16 + r_l + h * 8;
                float v0 = fmaxf(acc[mi][ni][h * 2 + 0] + bb.x, 0.f);
                float v1 = fmaxf(acc[mi][ni][h * 2 + 1] + bb.y, 0.f);
                split_store(Eh, El, (size_t)r * DD + col, v0, v1);
            }
        }
}

// ===========================================================================
// k_mpart_mma: split-K partials of M_z = e_zᵀ @ X (trans-A ldmatrix).
// grid (2, 2, 32) x 256, 4-stage ring.
// ===========================================================================
#define ES_ELEM(b, r, c) sEs[(b) * 4352 + (r) * 136 + (c)]
#define XS_ELEM(b, r, c) sXs[(b) * 4352 + (r) * 136 + (c)]

__global__ void __launch_bounds__(256, 2)
k_mpart_mma()
{
    const int mat = blockIdx.z >> 4, split = blockIdx.z & 15;
    const bf16* Ap[3] = {g_eh[mat], g_eh[mat], g_el[mat]};
    const bf16* Bp[3] = {g_Xh, g_Xl, g_Xh};
    float* __restrict__ Cp = g_Mpart[mat][split];

    extern __shared__ __align__(16) char sm_raw[];
    bf16* sEs = (bf16*)sm_raw;
    bf16* sXs = (bf16*)(sm_raw + 34816);

    const int tid = threadIdx.x;
    const int lane = tid & 31, w = tid >> 5;
    const int m0w = (w >> 2) * 64, n0w = (w & 3) * 32;
    const int mBase = blockIdx.y * 128, nBase = blockIdx.x * 128;
    const int i0 = split * (NEDGE / SPLITK);

    const int c0r = tid >> 4, c0o = (tid & 15) * 8;
    const int c1r = c0r + 16;

    auto prefetch = [&](int it, int bufn) {
        const int pass = it >> 4;
        const int e0 = i0 + (it & 15) * 32;
        const bf16* __restrict__ E = Ap[pass];
        const bf16* __restrict__ X = Bp[pass];
        cpa16(&ES_ELEM(bufn, c0r, c0o), E + (size_t)(e0 + c0r) * DD + mBase + c0o);
        cpa16(&ES_ELEM(bufn, c1r, c0o), E + (size_t)(e0 + c1r) * DD + mBase + c0o);
        cpa16(&XS_ELEM(bufn, c0r, c0o), X + (size_t)(e0 + c0r) * DD + nBase + c0o);
        cpa16(&XS_ELEM(bufn, c1r, c0o), X + (size_t)(e0 + c1r) * DD + nBase + c0o);
        cpa_commit();
    };

    const int t = lane >> 3;
    const int akro = (t >> 1) * 8 + (lane & 7);
    const int amco = (t & 1) * 8;
    const int bro2 = (lane & 7) + ((lane >> 3) & 1) * 8;
    const int bco2 = (lane >> 4) * 8;

    float acc[4][4][4] = {};
    prefetch(0, 0);
    prefetch(1, 1);
    prefetch(2, 2);
    for (int it = 0; it < 48; ++it) {
        cpa_wait2();
        __syncthreads();
        if (it + 3 < 48) prefetch(it + 3, (it + 3) & 3);
        else cpa_commit();
        const int buf = it & 3;
#pragma unroll
        for (int ki = 0; ki < 2; ++ki) {
            u32 a[4][4], bq[2][4];
#pragma unroll
            for (int mi = 0; mi < 4; ++mi)
                ldsm_x4_t(a[mi], saddr(&ES_ELEM(buf, ki * 16 + akro, m0w + mi * 16 + amco)));
#pragma unroll
            for (int nj = 0; nj < 2; ++nj)
                ldsm_x4_t(bq[nj], saddr(&XS_ELEM(buf, ki * 16 + bro2, n0w + nj * 16 + bco2)));
#pragma unroll
            for (int mi = 0; mi < 4; ++mi)
#pragma unroll
                for (int ni = 0; ni < 4; ++ni)
                    mma_bf16(acc[mi][ni], a[mi], &bq[ni >> 1][(ni & 1) * 2]);
        }
    }

    const int r_l = lane >> 2, c_l = (lane & 3) * 2;
#pragma unroll
    for (int mi = 0; mi < 4; ++mi)
#pragma unroll
        for (int ni = 0; ni < 4; ++ni) {
            const int col = nBase + n0w + ni * 8 + c_l;
#pragma unroll
            for (int h = 0; h < 2; ++h) {
                const int r = mBase + m0w + mi * 16 + r_l + h * 8;
                float2 v = make_float2(acc[mi][ni][h * 2 + 0], acc[mi][ni][h * 2 + 1]);
                *(float2*)&Cp[(size_t)r * DD + col] = v;
            }
        }
}

// ===========================================================================
// k_mreduce: 4-way thread-split + deterministic shfl_xor tree. grid 512 x 256.
// ===========================================================================
__global__ void k_mreduce()
{
    const int gid = blockIdx.x * 256 + threadIdx.x;   // 0..131071
    const int q4 = (gid & 3) * 4;
    const int o = gid >> 2;                           // 0..32767
    const int mat = o >> 14;
    const int o4 = (o & 16383) * 4;
    float4 s = *(const float4*)&g_Mpart[mat][q4][o4];
#pragma unroll
    for (int p = 1; p < 4; p++) {
        const float4 v = *(const float4*)&g_Mpart[mat][q4 + p][o4];
        s.x += v.x; s.y += v.y; s.z += v.z; s.w += v.w;
    }
#pragma unroll
    for (int d = 1; d <= 2; d <<= 1) {
        s.x += __shfl_xor_sync(0xffffffffu, s.x, d);
        s.y += __shfl_xor_sync(0xffffffffu, s.y, d);
        s.z += __shfl_xor_sync(0xffffffffu, s.z, d);
        s.w += __shfl_xor_sync(0xffffffffu, s.w, d);
    }
    if ((gid & 3) == 0) {
        const float sc = 1.0f / DD;
        s.x *= sc; s.y *= sc; s.z *= sc; s.w *= sc;
        *(float4*)&g_M[mat][o4] = s;
    }
}

// ===========================================================================
// k_p: P partials = M_z @ W3b_z, split-K x4 (fp32). grid (8, 8, 8) x 256.
// ===========================================================================
__global__ void k_p(const float* __restrict__ W3)
{
    const int mat = blockIdx.z >> 2, ks = blockIdx.z & 3;
    const float* __restrict__ A = g_M[mat];
    const float* __restrict__ B = W3 + (size_t)(DD + mat * DD) * DD;
    float* __restrict__ Cp = g_Ppart[mat][ks];

    __shared__ __align__(16) float As[32][68];
    __shared__ __align__(16) float Bs[64][36];

    const int tid = threadIdx.x;
    const int mBase = blockIdx.y * 32, nBase = blockIdx.x * 32, k0 = ks * 64;

    {
        const int c0 = tid, c1 = tid + 256;
        cpa16(&As[c0 >> 4][(c0 & 15) * 4], &A[(size_t)(mBase + (c0 >> 4)) * DD + k0 + (c0 & 15) * 4]);
        cpa16(&As[c1 >> 4][(c1 & 15) * 4], &A[(size_t)(mBase + (c1 >> 4)) * DD + k0 + (c1 & 15) * 4]);
        cpa16(&Bs[c0 >> 3][(c0 & 7) * 4], &B[(size_t)(k0 + (c0 >> 3)) * DD + nBase + (c0 & 7) * 4]);
        cpa16(&Bs[c1 >> 3][(c1 & 7) * 4], &B[(size_t)(k0 + (c1 >> 3)) * DD + nBase + (c1 & 7) * 4]);
        cpa_commit(); cpa_wait0();
        __syncthreads();
    }

    const int ty = tid >> 4, tx = tid & 15;
    float a00 = 0.f, a01 = 0.f, a10 = 0.f, a11 = 0.f;
#pragma unroll
    for (int kk = 0; kk < 64; kk++) {
        const float av0 = As[ty * 2 + 0][kk];
        const float av1 = As[ty * 2 + 1][kk];
        const float2 bv = *(const float2*)&Bs[kk][tx * 2];
        a00 = fmaf(av0, bv.x, a00); a01 = fmaf(av0, bv.y, a01);
        a10 = fmaf(av1, bv.x, a10); a11 = fmaf(av1, bv.y, a11);
    }
    *(float2*)&Cp[(size_t)(mBase + ty * 2 + 0) * DD + nBase + tx * 2] = make_float2(a00, a01);
    *(float2*)&Cp[(size_t)(mBase + ty * 2 + 1) * DD + nBase + tx * 2] = make_float2(a10, a11);
}

// ===========================================================================
// k_pcvt: 2-way thread-split reduce + hi/lo convert. grid 256 x 256.
// ===========================================================================
__global__ void k_pcvt()
{
    const int gid = blockIdx.x * 256 + threadIdx.x;   // 0..65535
    const int q2 = (gid & 1) * 2;
    const int o = gid >> 1;                            // 0..32767
    const int mat = o >> 14;
    const int o4 = (o & 16383) * 4;
    float4 s = *(const float4*)&g_Ppart[mat][q2][o4];
    {
        const float4 v = *(const float4*)&g_Ppart[mat][q2 + 1][o4];
        s.x += v.x; s.y += v.y; s.z += v.z; s.w += v.w;
    }
    s.x += __shfl_xor_sync(0xffffffffu, s.x, 1);
    s.y += __shfl_xor_sync(0xffffffffu, s.y, 1);
    s.z += __shfl_xor_sync(0xffffffffu, s.z, 1);
    s.w += __shfl_xor_sync(0xffffffffu, s.w, 1);
    if ((gid & 1) == 0) {
        split_store(g_Ph[mat], g_Pl[mat], o4,     s.x, s.y);
        split_store(g_Ph[mat], g_Pl[mat], o4 + 2, s.z, s.w);
    }
}

// ===========================================================================
// k_final_mma: out = relu(X@W3a + e1@P1 + e2@P2 + b3). 7 passes:
// X@W3a hi-only (that term is ~5% of the output magnitude; its bf16
// correction passes are below the error budget), e@P full 3-term.
// grid (2, 64) x 256.
// ===========================================================================
__global__ void __launch_bounds__(256, 2)
k_final_mma(const float* __restrict__ b3, float* __restrict__ out)
{
    const bf16* Ap[7] = {g_Xh,
                         g_eh[0], g_eh[0], g_el[0],
                         g_eh[1], g_eh[1], g_el[1]};
    const bf16* Bp[7] = {g_W3ah,
                         g_Ph[0], g_Pl[0], g_Ph[0],
                         g_Ph[1], g_Pl[1], g_Ph[1]};

    const int rowBase = blockIdx.y * 128, colBase = blockIdx.x * 128;
    float acc[4][4][4] = {};
    mma_core_rowA<7>(Ap, Bp, rowBase, colBase, acc);

    const int lane = threadIdx.x & 31, w = threadIdx.x >> 5;
    const int m0w = (w >> 2) * 64, n0w = (w & 3) * 32;
    const int r_l = lane >> 2, c_l = (lane & 3) * 2;
#pragma unroll
    for (int mi = 0; mi < 4; ++mi)
#pragma unroll
        for (int ni = 0; ni < 4; ++ni) {
            const int col = colBase + n0w + ni * 8 + c_l;
            const float2 bb = *(const float2*)&b3[col];
#pragma unroll
            for (int h = 0; h < 2; ++h) {
                const int r = rowBase + m0w + mi * 16 + r_l + h * 8;
                float2 v;
                v.x = fmaxf(acc[mi][ni][h * 2 + 0] + bb.x, 0.f);
                v.y = fmaxf(acc[mi][ni][h * 2 + 1] + bb.y, 0.f);
                *(float2*)&out[(size_t)r * DD + col] = v;
            }
        }
}

// ---------------------------------------------------------------------------
// Inputs (metadata order):
// 0 edge_pred[8192] f32 | 1 edge_corner[8192,2] i64 | 2 all_corners[4096,2] f32
// 3 edge_x[8192,256] f32 | 4 image_x[1024] f32 | 5 W1[256,256] | 6 b1[256]
// 7 W2[256,256] | 8 b2[256] | 9 W3[768,256] | 10 b3[256]
// Output: [8192, 256] f32
// ---------------------------------------------------------------------------
extern "C" void kernel_launch(void* const* d_in, const int* in_sizes, int n_in,
                              void* d_out, int out_size)
{
    (void)in_sizes; (void)n_in; (void)out_size;
    const float* X  = (const float*)d_in[3];
    const float* W1 = (const float*)d_in[5];
    const float* b1 = (const float*)d_in[6];
    const float* W2 = (const float*)d_in[7];
    const float* b2 = (const float*)d_in[8];
    const float* W3 = (const float*)d_in[9];
    const float* b3 = (const float*)d_in[10];
    float* out = (float*)d_out;

    const int SMEM_CORE  = 40960 + 34816;  // 4-stage: 75776 B
    const int SMEM_MPART = 2 * 34816;      // 4-stage: 69632 B
    cudaFuncSetAttribute(k_e_mma, cudaFuncAttributeMaxDynamicSharedMemorySize, SMEM_CORE);
    cudaFuncSetAttribute(k_final_mma, cudaFuncAttributeMaxDynamicSharedMemorySize, SMEM_CORE);
    cudaFuncSetAttribute(k_mpart_mma, cudaFuncAttributeMaxDynamicSharedMemorySize, SMEM_MPART);

    k_cvt<<<2240, 256>>>((const float4*)X, (const float4*)W1,
                         (const float4*)W2, (const float4*)W3);
    k_e_mma<<<dim3(2, 64, 2), 256, SMEM_CORE>>>(b1, b2);
    k_mpart_mma<<<dim3(2, 2, 32), 256, SMEM_MPART>>>();
    k_mreduce<<<512, 256>>>();
    k_p<<<dim3(8, 8, 8), 256>>>(W3);
    k_pcvt<<<256, 256>>>();
    k_final_mma<<<dim3(2, 64), 256, SMEM_CORE>>>(b3, out);
}

// round 9
// speedup vs baseline: 2.6775x; 1.0608x over previous
#include <cuda_runtime.h>
#include <cuda_bf16.h>

#define NEDGE 8192
#define DD    256
#define SPLITK 16

typedef __nv_bfloat16 bf16;
typedef unsigned int u32;

// ---------------- scratch (device globals; no allocation allowed) ----------
__device__ __align__(16) bf16 g_Xh[NEDGE * DD], g_Xl[NEDGE * DD];
__device__ __align__(16) bf16 g_eh[2][NEDGE * DD], g_el[2][NEDGE * DD];
__device__ __align__(16) bf16 g_W1h[DD * DD], g_W1l[DD * DD];
__device__ __align__(16) bf16 g_W2h[DD * DD], g_W2l[DD * DD];
__device__ __align__(16) bf16 g_W3ah[DD * DD], g_W3al[DD * DD];
__device__ __align__(16) bf16 g_Ph[2][DD * DD], g_Pl[2][DD * DD];
__device__ float g_Mpart[2][SPLITK][DD * DD];
__device__ float g_M[2][DD * DD];

// ---------------- helpers ---------------------------------------------------
__device__ __forceinline__ void cpa16(void* dst, const void* src) {
    unsigned s = (unsigned)__cvta_generic_to_shared(dst);
    asm volatile("cp.async.cg.shared.global [%0], [%1], 16;" :: "r"(s), "l"(src));
}
__device__ __forceinline__ void cpa_commit() { asm volatile("cp.async.commit_group;"); }
__device__ __forceinline__ void cpa_wait0()  { asm volatile("cp.async.wait_group 0;"); }
__device__ __forceinline__ void cpa_wait1()  { asm volatile("cp.async.wait_group 1;"); }

__device__ __forceinline__ unsigned saddr(const void* p) {
    return (unsigned)__cvta_generic_to_shared(p);
}
__device__ __forceinline__ void ldsm_x4(u32* r, unsigned a) {
    asm volatile("ldmatrix.sync.aligned.m8n8.x4.shared.b16 {%0,%1,%2,%3}, [%4];"
        : "=r"(r[0]), "=r"(r[1]), "=r"(r[2]), "=r"(r[3]) : "r"(a));
}
__device__ __forceinline__ void ldsm_x4_t(u32* r, unsigned a) {
    asm volatile("ldmatrix.sync.aligned.m8n8.x4.trans.shared.b16 {%0,%1,%2,%3}, [%4];"
        : "=r"(r[0]), "=r"(r[1]), "=r"(r[2]), "=r"(r[3]) : "r"(a));
}
__device__ __forceinline__ void mma_bf16(float* d, const u32* a, const u32* b) {
    asm volatile(
        "mma.sync.aligned.m16n8k16.row.col.f32.bf16.bf16.f32 "
        "{%0,%1,%2,%3}, {%4,%5,%6,%7}, {%8,%9}, {%0,%1,%2,%3};"
        : "+f"(d[0]), "+f"(d[1]), "+f"(d[2]), "+f"(d[3])
        : "r"(a[0]), "r"(a[1]), "r"(a[2]), "r"(a[3]), "r"(b[0]), "r"(b[1]));
}
__device__ __forceinline__ void split_store(bf16* Hp, bf16* Lp, size_t off,
                                            float v0, float v1) {
    bf16 h0 = __float2bfloat16(v0), h1 = __float2bfloat16(v1);
    bf16 l0 = __float2bfloat16(v0 - __bfloat162float(h0));
    bf16 l1 = __float2bfloat16(v1 - __bfloat162float(h1));
    __nv_bfloat162 H; H.x = h0; H.y = h1;
    __nv_bfloat162 L; L.x = l0; L.y = l1;
    *reinterpret_cast<__nv_bfloat162*>(Hp + off) = H;
    *reinterpret_cast<__nv_bfloat162*>(Lp + off) = L;
}

// ===========================================================================
// k_cvt: float4-vectorized hi/lo conversion of X and W1/W2/W3a.
// grid 2240 x 256 (exact).
// ===========================================================================
__global__ void k_cvt(const float4* __restrict__ X4, const float4* __restrict__ W14,
                      const float4* __restrict__ W24, const float4* __restrict__ W34)
{
    const int idx = blockIdx.x * 256 + threadIdx.x;
    if (idx < 524288) {
        const float4 v = X4[idx];
        const size_t o = (size_t)idx * 4;
        split_store(g_Xh, g_Xl, o,     v.x, v.y);
        split_store(g_Xh, g_Xl, o + 2, v.z, v.w);
    } else {
        const int w = idx - 524288;
        const int which = w >> 14;
        const int off4 = w & 16383;
        const float4* S = (which == 0) ? W14 : (which == 1) ? W24 : W34;
        bf16* Hd = (which == 0) ? g_W1h : (which == 1) ? g_W2h : g_W3ah;
        bf16* Ld = (which == 0) ? g_W1l : (which == 1) ? g_W2l : g_W3al;
        const float4 v = S[off4];
        const size_t o = (size_t)off4 * 4;
        split_store(Hd, Ld, o,     v.x, v.y);
        split_store(Hd, Ld, o + 2, v.z, v.w);
    }
}

// ===========================================================================
// Core: multi-pass bf16 MMA GEMM. Block tile 128x128, 8 warps (2m x 4n),
// warp tile 64x32, k-tile 64 (4 ki sub-steps), 3-stage cp.async ring.
// smem: As 3 x 128 x 72 (55296 B) + Bs 3 x 64 x 136 (52224 B) = 107520 B.
// ===========================================================================
#define AS_ELEM(b, r, c) sAs[(b) * 9216 + (r) * 72 + (c)]
#define BS_ELEM(b, r, c) sBs[(b) * 8704 + (r) * 136 + (c)]

template <int NPASS>
__device__ __forceinline__ void mma_core_rowA(
    const bf16* const* Ap, const bf16* const* Bp,
    int rowBase, int colBase, float (&acc)[4][4][4])
{
    extern __shared__ __align__(16) char sm_raw[];
    bf16* sAs = (bf16*)sm_raw;
    bf16* sBs = (bf16*)(sm_raw + 55296);

    const int tid = threadIdx.x;
    const int lane = tid & 31, w = tid >> 5;
    const int m0w = (w >> 2) * 64, n0w = (w & 3) * 32;

    auto prefetch = [&](int it, int bufn) {
        const int pass = it >> 2;
        const int k0 = (it & 3) * 64;
        const bf16* __restrict__ A = Ap[pass];
        const bf16* __restrict__ B = Bp[pass];
#pragma unroll
        for (int i = 0; i < 4; ++i) {
            const int ca = tid + 256 * i;               // A: 128 rows x 64 k
            const int ar = ca >> 3, ao = (ca & 7) * 8;
            cpa16(&AS_ELEM(bufn, ar, ao), A + (size_t)(rowBase + ar) * DD + k0 + ao);
            const int cb = tid + 256 * i;               // B: 64 k x 128 n
            const int br = cb >> 4, bo = (cb & 15) * 8;
            cpa16(&BS_ELEM(bufn, br, bo), B + (size_t)(k0 + br) * DD + colBase + bo);
        }
        cpa_commit();
    };

    const int t = lane >> 3;
    const int aro = (t & 1) * 8 + (lane & 7);
    const int aco = (t >> 1) * 8;
    const int bro2 = (lane & 7) + ((lane >> 3) & 1) * 8;
    const int bco2 = (lane >> 4) * 8;

    constexpr int NIT = NPASS * 4;
    prefetch(0, 0);
    prefetch(1, 1);
    for (int it = 0; it < NIT; ++it) {
        cpa_wait1();
        __syncthreads();
        if (it + 2 < NIT) prefetch(it + 2, (it + 2) % 3);
        else cpa_commit();   // keep wait-group arithmetic exact
        const int buf = it % 3;
#pragma unroll
        for (int ki = 0; ki < 4; ++ki) {
            u32 a[4][4], bq[2][4];
#pragma unroll
            for (int mi = 0; mi < 4; ++mi)
                ldsm_x4(a[mi], saddr(&AS_ELEM(buf, m0w + mi * 16 + aro, ki * 16 + aco)));
#pragma unroll
            for (int nj = 0; nj < 2; ++nj)
                ldsm_x4_t(bq[nj], saddr(&BS_ELEM(buf, ki * 16 + bro2, n0w + nj * 16 + bco2)));
#pragma unroll
            for (int mi = 0; mi < 4; ++mi)
#pragma unroll
                for (int ni = 0; ni < 4; ++ni)
                    mma_bf16(acc[mi][ni], a[mi], &bq[ni >> 1][(ni & 1) * 2]);
        }
    }
}

// ===========================================================================
// k_e_mma: e_z = relu(X @ W_z + b_z) -> bf16 hi/lo. grid (2, 64, 2) x 256.
// ===========================================================================
__global__ void __launch_bounds__(256, 2)
k_e_mma(const float* __restrict__ b1, const float* __restrict__ b2)
{
    const int z = blockIdx.z;
    const bf16* Ap[3] = {g_Xh, g_Xh, g_Xl};
    const bf16* Bp[3] = {z ? g_W2h : g_W1h, z ? g_W2l : g_W1l, z ? g_W2h : g_W1h};
    const float* __restrict__ bias = z ? b2 : b1;
    bf16* __restrict__ Eh = g_eh[z];
    bf16* __restrict__ El = g_el[z];

    const int rowBase = blockIdx.y * 128, colBase = blockIdx.x * 128;
    float acc[4][4][4] = {};
    mma_core_rowA<3>(Ap, Bp, rowBase, colBase, acc);

    const int lane = threadIdx.x & 31, w = threadIdx.x >> 5;
    const int m0w = (w >> 2) * 64, n0w = (w & 3) * 32;
    const int r_l = lane >> 2, c_l = (lane & 3) * 2;
#pragma unroll
    for (int mi = 0; mi < 4; ++mi)
#pragma unroll
        for (int ni = 0; ni < 4; ++ni) {
            const int col = colBase + n0w + ni * 8 + c_l;
            const float2 bb = *(const float2*)&bias[col];
#pragma unroll
            for (int h = 0; h < 2; ++h) {
                const int r = rowBase + m0w + mi * 16 + r_l + h * 8;
                float v0 = fmaxf(acc[mi][ni][h * 2 + 0] + bb.x, 0.f);
                float v1 = fmaxf(acc[mi][ni][h * 2 + 1] + bb.y, 0.f);
                split_store(Eh, El, (size_t)r * DD + col, v0, v1);
            }
        }
}

// ===========================================================================
// k_mpart_mma: split-K partials of M_z = e_zᵀ @ X (trans-A ldmatrix).
// grid (2, 2, 32) x 256, k-tile 64, 3-stage ring.
// smem: Es 3 x 64 x 136 + Xs 3 x 64 x 136 = 104448 B.
// ===========================================================================
#define ES_ELEM(b, r, c) sEs[(b) * 8704 + (r) * 136 + (c)]
#define XS_ELEM(b, r, c) sXs[(b) * 8704 + (r) * 136 + (c)]

__global__ void __launch_bounds__(256, 2)
k_mpart_mma()
{
    const int mat = blockIdx.z >> 4, split = blockIdx.z & 15;
    const bf16* Ap[3] = {g_eh[mat], g_eh[mat], g_el[mat]};
    const bf16* Bp[3] = {g_Xh, g_Xl, g_Xh};
    float* __restrict__ Cp = g_Mpart[mat][split];

    extern __shared__ __align__(16) char sm_raw[];
    bf16* sEs = (bf16*)sm_raw;
    bf16* sXs = (bf16*)(sm_raw + 52224);

    const int tid = threadIdx.x;
    const int lane = tid & 31, w = tid >> 5;
    const int m0w = (w >> 2) * 64, n0w = (w & 3) * 32;
    const int mBase = blockIdx.y * 128, nBase = blockIdx.x * 128;
    const int i0 = split * (NEDGE / SPLITK);

    auto prefetch = [&](int it, int bufn) {
        const int pass = it >> 3;
        const int e0 = i0 + (it & 7) * 64;
        const bf16* __restrict__ E = Ap[pass];
        const bf16* __restrict__ X = Bp[pass];
#pragma unroll
        for (int i = 0; i < 4; ++i) {
            const int c = tid + 256 * i;                // 64 rows x 128 cols
            const int r = c >> 4, o = (c & 15) * 8;
            cpa16(&ES_ELEM(bufn, r, o), E + (size_t)(e0 + r) * DD + mBase + o);
            cpa16(&XS_ELEM(bufn, r, o), X + (size_t)(e0 + r) * DD + nBase + o);
        }
        cpa_commit();
    };

    const int t = lane >> 3;
    const int akro = (t >> 1) * 8 + (lane & 7);
    const int amco = (t & 1) * 8;
    const int bro2 = (lane & 7) + ((lane >> 3) & 1) * 8;
    const int bco2 = (lane >> 4) * 8;

    float acc[4][4][4] = {};
    prefetch(0, 0);
    prefetch(1, 1);
    for (int it = 0; it < 24; ++it) {
        cpa_wait1();
        __syncthreads();
        if (it + 2 < 24) prefetch(it + 2, (it + 2) % 3);
        else cpa_commit();
        const int buf = it % 3;
#pragma unroll
        for (int ki = 0; ki < 4; ++ki) {
            u32 a[4][4], bq[2][4];
#pragma unroll
            for (int mi = 0; mi < 4; ++mi)
                ldsm_x4_t(a[mi], saddr(&ES_ELEM(buf, ki * 16 + akro, m0w + mi * 16 + amco)));
#pragma unroll
            for (int nj = 0; nj < 2; ++nj)
                ldsm_x4_t(bq[nj], saddr(&XS_ELEM(buf, ki * 16 + bro2, n0w + nj * 16 + bco2)));
#pragma unroll
            for (int mi = 0; mi < 4; ++mi)
#pragma unroll
                for (int ni = 0; ni < 4; ++ni)
                    mma_bf16(acc[mi][ni], a[mi], &bq[ni >> 1][(ni & 1) * 2]);
        }
    }

    const int r_l = lane >> 2, c_l = (lane & 3) * 2;
#pragma unroll
    for (int mi = 0; mi < 4; ++mi)
#pragma unroll
        for (int ni = 0; ni < 4; ++ni) {
            const int col = nBase + n0w + ni * 8 + c_l;
#pragma unroll
            for (int h = 0; h < 2; ++h) {
                const int r = mBase + m0w + mi * 16 + r_l + h * 8;
                float2 v = make_float2(acc[mi][ni][h * 2 + 0], acc[mi][ni][h * 2 + 1]);
                *(float2*)&Cp[(size_t)r * DD + col] = v;
            }
        }
}

// ===========================================================================
// k_mreduce: 4-way thread-split + deterministic shfl_xor tree. grid 512 x 256.
// ===========================================================================
__global__ void k_mreduce()
{
    const int gid = blockIdx.x * 256 + threadIdx.x;   // 0..131071
    const int q4 = (gid & 3) * 4;
    const int o = gid >> 2;                           // 0..32767
    const int mat = o >> 14;
    const int o4 = (o & 16383) * 4;
    float4 s = *(const float4*)&g_Mpart[mat][q4][o4];
#pragma unroll
    for (int p = 1; p < 4; p++) {
        const float4 v = *(const float4*)&g_Mpart[mat][q4 + p][o4];
        s.x += v.x; s.y += v.y; s.z += v.z; s.w += v.w;
    }
#pragma unroll
    for (int d = 1; d <= 2; d <<= 1) {
        s.x += __shfl_xor_sync(0xffffffffu, s.x, d);
        s.y += __shfl_xor_sync(0xffffffffu, s.y, d);
        s.z += __shfl_xor_sync(0xffffffffu, s.z, d);
        s.w += __shfl_xor_sync(0xffffffffu, s.w, d);
    }
    if ((gid & 3) == 0) {
        const float sc = 1.0f / DD;
        s.x *= sc; s.y *= sc; s.z *= sc; s.w *= sc;
        *(float4*)&g_M[mat][o4] = s;
    }
}

// ===========================================================================
// k_p: P_z = M_z @ W3b_z (fp32, K=256 sequential) fused with hi/lo convert.
// 32x32 out tile, grid (8, 8, 2) x 256. Writes g_Ph/g_Pl directly.
// ===========================================================================
__global__ void k_p(const float* __restrict__ W3)
{
    const int mat = blockIdx.z;
    const float* __restrict__ A = g_M[mat];
    const float* __restrict__ B = W3 + (size_t)(DD + mat * DD) * DD;

    __shared__ __align__(16) float As[32][68];
    __shared__ __align__(16) float Bs[64][36];

    const int tid = threadIdx.x;
    const int mBase = blockIdx.y * 32, nBase = blockIdx.x * 32;
    const int ty = tid >> 4, tx = tid & 15;

    float a00 = 0.f, a01 = 0.f, a10 = 0.f, a11 = 0.f;

    for (int kt = 0; kt < DD; kt += 64) {
        const int c0 = tid, c1 = tid + 256;
        cpa16(&As[c0 >> 4][(c0 & 15) * 4], &A[(size_t)(mBase + (c0 >> 4)) * DD + kt + (c0 & 15) * 4]);
        cpa16(&As[c1 >> 4][(c1 & 15) * 4], &A[(size_t)(mBase + (c1 >> 4)) * DD + kt + (c1 & 15) * 4]);
        cpa16(&Bs[c0 >> 3][(c0 & 7) * 4], &B[(size_t)(kt + (c0 >> 3)) * DD + nBase + (c0 & 7) * 4]);
        cpa16(&Bs[c1 >> 3][(c1 & 7) * 4], &B[(size_t)(kt + (c1 >> 3)) * DD + nBase + (c1 & 7) * 4]);
        cpa_commit(); cpa_wait0();
        __syncthreads();
#pragma unroll
        for (int kk = 0; kk < 64; kk++) {
            const float av0 = As[ty * 2 + 0][kk];
            const float av1 = As[ty * 2 + 1][kk];
            const float2 bv = *(const float2*)&Bs[kk][tx * 2];
            a00 = fmaf(av0, bv.x, a00); a01 = fmaf(av0, bv.y, a01);
            a10 = fmaf(av1, bv.x, a10); a11 = fmaf(av1, bv.y, a11);
        }
        __syncthreads();
    }

    split_store(g_Ph[mat], g_Pl[mat], (size_t)(mBase + ty * 2 + 0) * DD + nBase + tx * 2, a00, a01);
    split_store(g_Ph[mat], g_Pl[mat], (size_t)(mBase + ty * 2 + 1) * DD + nBase + tx * 2, a10, a11);
}

// ===========================================================================
// k_final_mma: out = relu(X@W3a + e1@P1 + e2@P2 + b3). 7 passes:
// X@W3a hi-only (~5% of output magnitude; corrections below error budget),
// e@P full 3-term. grid (2, 64) x 256.
// ===========================================================================
__global__ void __launch_bounds__(256, 2)
k_final_mma(const float* __restrict__ b3, float* __restrict__ out)
{
    const bf16* Ap[7] = {g_Xh,
                         g_eh[0], g_eh[0], g_el[0],
                         g_eh[1], g_eh[1], g_el[1]};
    const bf16* Bp[7] = {g_W3ah,
                         g_Ph[0], g_Pl[0], g_Ph[0],
                         g_Ph[1], g_Pl[1], g_Ph[1]};

    const int rowBase = blockIdx.y * 128, colBase = blockIdx.x * 128;
    float acc[4][4][4] = {};
    mma_core_rowA<7>(Ap, Bp, rowBase, colBase, acc);

    const int lane = threadIdx.x & 31, w = threadIdx.x >> 5;
    const int m0w = (w >> 2) * 64, n0w = (w & 3) * 32;
    const int r_l = lane >> 2, c_l = (lane & 3) * 2;
#pragma unroll
    for (int mi = 0; mi < 4; ++mi)
#pragma unroll
        for (int ni = 0; ni < 4; ++ni) {
            const int col = colBase + n0w + ni * 8 + c_l;
            const float2 bb = *(const float2*)&b3[col];
#pragma unroll
            for (int h = 0; h < 2; ++h) {
                const int r = rowBase + m0w + mi * 16 + r_l + h * 8;
                float2 v;
                v.x = fmaxf(acc[mi][ni][h * 2 + 0] + bb.x, 0.f);
                v.y = fmaxf(acc[mi][ni][h * 2 + 1] + bb.y, 0.f);
                *(float2*)&out[(size_t)r * DD + col] = v;
            }
        }
}

// ---------------------------------------------------------------------------
// Inputs (metadata order):
// 0 edge_pred[8192] f32 | 1 edge_corner[8192,2] i64 | 2 all_corners[4096,2] f32
// 3 edge_x[8192,256] f32 | 4 image_x[1024] f32 | 5 W1[256,256] | 6 b1[256]
// 7 W2[256,256] | 8 b2[256] | 9 W3[768,256] | 10 b3[256]
// Output: [8192, 256] f32
// ---------------------------------------------------------------------------
extern "C" void kernel_launch(void* const* d_in, const int* in_sizes, int n_in,
                              void* d_out, int out_size)
{
    (void)in_sizes; (void)n_in; (void)out_size;
    const float* X  = (const float*)d_in[3];
    const float* W1 = (const float*)d_in[5];
    const float* b1 = (const float*)d_in[6];
    const float* W2 = (const float*)d_in[7];
    const float* b2 = (const float*)d_in[8];
    const float* W3 = (const float*)d_in[9];
    const float* b3 = (const float*)d_in[10];
    float* out = (float*)d_out;

    const int SMEM_CORE  = 55296 + 52224;  // 107520 B (3-stage, k-tile 64)
    const int SMEM_MPART = 2 * 52224;      // 104448 B
    cudaFuncSetAttribute(k_e_mma, cudaFuncAttributeMaxDynamicSharedMemorySize, SMEM_CORE);
    cudaFuncSetAttribute(k_final_mma, cudaFuncAttributeMaxDynamicSharedMemorySize, SMEM_CORE);
    cudaFuncSetAttribute(k_mpart_mma, cudaFuncAttributeMaxDynamicSharedMemorySize, SMEM_MPART);

    k_cvt<<<2240, 256>>>((const float4*)X, (const float4*)W1,
                         (const float4*)W2, (const float4*)W3);
    k_e_mma<<<dim3(2, 64, 2), 256, SMEM_CORE>>>(b1, b2);
    k_mpart_mma<<<dim3(2, 2, 32), 256, SMEM_MPART>>>();
    k_mreduce<<<512, 256>>>();
    k_p<<<dim3(8, 8, 2), 256>>>(W3);
    k_final_mma<<<dim3(2, 64), 256, SMEM_CORE>>>(b3, out);
}